// round 12
// baseline (speedup 1.0000x reference)
#include <cuda_runtime.h>
#include <math.h>
#include <stdint.h>

#define NST 8192
#define CC  512
#define HH  128

// ---------------- scratch (device globals; no allocation allowed) ----------
__device__ float g_S[(size_t)NST * NST];        // 256 MB score matrix
__device__ float g_L[(size_t)NST * CC];         // logits [C,N] then c2s [N,C]
__device__ float g_hidden1[CC * HH];
__device__ float g_hiddenB[CC * HH];
__device__ float g_csmv[CC];
__device__ float g_xnorm[NST];
__device__ float g_normB[CC];
__device__ int   g_keep1[CC];
__device__ float g_hnorm[NST];
__device__ float g_norm2[NST];
__device__ int   g_keep2[NST];
__device__ float g_colsum[NST];
__device__ int   g_idx3[NST * 3];
__device__ float g_val3[NST * 3];
__device__ float g_ppre[(size_t)NST * HH];
__device__ float g_pshared[(size_t)NST * HH];
__device__ float g_pback[(size_t)NST * HH];
__device__ float g_outps[(size_t)NST * HH];
__device__ float g_hshared[(size_t)NST * HH];
__device__ float g_hidden2[(size_t)NST * HH];
__device__ float g_hinfopre[(size_t)NST * HH];
__device__ float g_hinfo[(size_t)NST * HH];
__device__ float g_hback[(size_t)NST * HH];
__device__ float g_ouths[(size_t)NST * HH];
__device__ float g_indiv[(size_t)NST * HH];
__device__ float g_outindi[(size_t)NST * HH];

// ---------------- generic 128x128x8 SGEMM ----------------------------------
// C[M,N] = A[M,K] @ (TRANSB ? B[N,K]^T : B[K,N])
// EPI: 0 plain, 1 cosine(na,nb)+keep-mask(-inf), 2 +bias, 3 +bias+leakyrelu
// gridDim.z > 1 => split-K partial sums via atomicAdd (EPI 0, C pre-zeroed)
template <int EPI, int TRANSB>
__global__ void __launch_bounds__(256)
gemm128(const float* __restrict__ A, const float* __restrict__ B, float* __restrict__ C,
        int M, int N, int K,
        const float* __restrict__ na, const float* __restrict__ nb,
        const int* __restrict__ keep, const float* __restrict__ bias)
{
    __shared__ float As[8][128];
    __shared__ float Bs[8][128];
    const int tid = threadIdx.x;
    const int tx = tid & 15, ty = tid >> 4;
    const int m0 = blockIdx.y * 128, n0 = blockIdx.x * 128;

    const int lr = tid >> 1;          // 0..127 tile row
    const int lk = (tid & 1) * 4;     // 0 or 4  k offset
    const int bkr = tid >> 5;         // 0..7    NN B-load row
    const int bc  = (tid & 31) * 4;   // 0..124  NN B-load col

    float acc[8][8];
#pragma unroll
    for (int i = 0; i < 8; i++)
#pragma unroll
        for (int j = 0; j < 8; j++) acc[i][j] = 0.f;

    const int kper = K / gridDim.z;
    const int kb = blockIdx.z * kper;

    for (int k0 = kb; k0 < kb + kper; k0 += 8) {
        float4 av = *(const float4*)(A + (size_t)(m0 + lr) * K + (k0 + lk));
        As[lk + 0][lr] = av.x; As[lk + 1][lr] = av.y;
        As[lk + 2][lr] = av.z; As[lk + 3][lr] = av.w;
        if (TRANSB) {
            float4 bv = *(const float4*)(B + (size_t)(n0 + lr) * K + (k0 + lk));
            Bs[lk + 0][lr] = bv.x; Bs[lk + 1][lr] = bv.y;
            Bs[lk + 2][lr] = bv.z; Bs[lk + 3][lr] = bv.w;
        } else {
            float4 bv = *(const float4*)(B + (size_t)(k0 + bkr) * N + (n0 + bc));
            *(float4*)(&Bs[bkr][bc]) = bv;
        }
        __syncthreads();
#pragma unroll
        for (int k = 0; k < 8; k++) {
            float4 a0 = *(const float4*)(&As[k][ty * 4]);
            float4 a1 = *(const float4*)(&As[k][ty * 4 + 64]);
            float4 b0 = *(const float4*)(&Bs[k][tx * 4]);
            float4 b1 = *(const float4*)(&Bs[k][tx * 4 + 64]);
            float ar[8] = {a0.x, a0.y, a0.z, a0.w, a1.x, a1.y, a1.z, a1.w};
            float br[8] = {b0.x, b0.y, b0.z, b0.w, b1.x, b1.y, b1.z, b1.w};
#pragma unroll
            for (int i = 0; i < 8; i++)
#pragma unroll
                for (int j = 0; j < 8; j++)
                    acc[i][j] = fmaf(ar[i], br[j], acc[i][j]);
        }
        __syncthreads();
    }

    const bool atom = (gridDim.z > 1);
#pragma unroll
    for (int ih = 0; ih < 2; ih++) {
#pragma unroll
        for (int i = 0; i < 4; i++) {
            const int row = m0 + ih * 64 + ty * 4 + i;
            float nrow = 0.f;
            if (EPI == 1) nrow = na[row];
#pragma unroll
            for (int jh = 0; jh < 2; jh++) {
                const int cb = n0 + jh * 64 + tx * 4;
                float v[4];
#pragma unroll
                for (int j = 0; j < 4; j++) {
                    float xv = acc[ih * 4 + i][jh * 4 + j];
                    const int col = cb + j;
                    if (EPI == 1) {
                        float d = nrow * nb[col];
                        xv = (d == 0.f) ? 0.f : xv / d;
                        if (!keep[col]) xv = __int_as_float(0xff800000); // -inf
                    } else if (EPI == 2) {
                        xv += bias[col];
                    } else if (EPI == 3) {
                        xv += bias[col];
                        xv = xv > 0.f ? xv : 0.01f * xv;
                    }
                    v[j] = xv;
                }
                float* cp = C + (size_t)row * N + cb;
                if (!atom) {
                    float4 o; o.x = v[0]; o.y = v[1]; o.z = v[2]; o.w = v[3];
                    *(float4*)cp = o;
                } else {
                    atomicAdd(cp + 0, v[0]); atomicAdd(cp + 1, v[1]);
                    atomicAdd(cp + 2, v[2]); atomicAdd(cp + 3, v[3]);
                }
            }
        }
    }
}

// ---------------- small kernels --------------------------------------------
__global__ void kzero(float* p, size_t n) {
    size_t i = (size_t)blockIdx.x * blockDim.x + threadIdx.x;
    size_t st = (size_t)gridDim.x * blockDim.x;
    for (; i < n; i += st) p[i] = 0.f;
}

__global__ void k_csmv(const int* __restrict__ cm, const float* __restrict__ mv) {
    int c = blockIdx.x * 128 + threadIdx.x;
    int y = blockIdx.y;
    const int chunk = NST / 16;
    float acc = 0.f;
    for (int n = y * chunk; n < (y + 1) * chunk; ++n)
        acc += (float)cm[(size_t)n * CC + c] * mv[n];
    atomicAdd(&g_csmv[c], acc);
}

// hidden1[c,:] = (1/(csmv[c]+1)) * sum_{n: cm[n,c]=1} mv[n]*x[n,:]
__global__ void k_cagg(const int* __restrict__ cm, const float* __restrict__ mv,
                       const float* __restrict__ x) {
    int c = blockIdx.x, tid = threadIdx.x; // 128 threads over H
    __shared__ float w[128];
    float acc = 0.f;
    for (int n0 = 0; n0 < NST; n0 += 128) {
        int n = n0 + tid;
        w[tid] = (float)cm[(size_t)n * CC + c] * mv[n];
        __syncthreads();
#pragma unroll 8
        for (int nn = 0; nn < 128; nn++) {
            float ww = w[nn];
            if (ww != 0.f) acc = fmaf(ww, x[(size_t)(n0 + nn) * HH + tid], acc);
        }
        __syncthreads();
    }
    g_hidden1[c * HH + tid] = acc / (g_csmv[c] + 1.f);
}

// per-row L2 norm and/or nonzero-rowsum flag (H=128, 128 threads)
__global__ void k_rowstats(const float* __restrict__ X, float* norm, int* keep) {
    int r = blockIdx.x, tid = threadIdx.x;
    float v = X[(size_t)r * HH + tid];
    float s = v, q = v * v;
#pragma unroll
    for (int o = 16; o; o >>= 1) {
        s += __shfl_xor_sync(0xffffffffu, s, o);
        q += __shfl_xor_sync(0xffffffffu, q, o);
    }
    __shared__ float ss[4], qq[4];
    int wi = tid >> 5, ln = tid & 31;
    if (!ln) { ss[wi] = s; qq[wi] = q; }
    __syncthreads();
    if (tid == 0) {
        float S = ss[0] + ss[1] + ss[2] + ss[3];
        float Q = qq[0] + qq[1] + qq[2] + qq[3];
        if (norm) norm[r] = sqrtf(Q);
        if (keep) keep[r] = (S != 0.f) ? 1 : 0;
    }
}

// in-place row softmax; row cached in dynamic smem (cols*4 bytes)
__global__ void k_rowsoftmax(float* __restrict__ X, int cols) {
    extern __shared__ float buf[];
    __shared__ float red[8];
    __shared__ float bc0;
    int r = blockIdx.x, tid = threadIdx.x; // 256 threads
    int wi = tid >> 5, ln = tid & 31;
    float* p = X + (size_t)r * cols;

    float mx = -INFINITY;
    for (int j = tid; j < cols; j += 256) { float v = p[j]; buf[j] = v; mx = fmaxf(mx, v); }
#pragma unroll
    for (int o = 16; o; o >>= 1) mx = fmaxf(mx, __shfl_xor_sync(0xffffffffu, mx, o));
    if (!ln) red[wi] = mx;
    __syncthreads();
    if (tid == 0) {
        float t = red[0];
#pragma unroll
        for (int k = 1; k < 8; k++) t = fmaxf(t, red[k]);
        bc0 = t;
    }
    __syncthreads();
    mx = bc0;

    float s = 0.f;
    for (int j = tid; j < cols; j += 256) { float e = expf(buf[j] - mx); buf[j] = e; s += e; }
#pragma unroll
    for (int o = 16; o; o >>= 1) s += __shfl_xor_sync(0xffffffffu, s, o);
    __syncthreads();
    if (!ln) red[wi] = s;
    __syncthreads();
    if (tid == 0) {
        float t = 0.f;
#pragma unroll
        for (int k = 0; k < 8; k++) t += red[k];
        bc0 = 1.f / t;
    }
    __syncthreads();
    float inv = bc0;
    for (int j = tid; j < cols; j += 256) p[j] = buf[j] * inv;
}

// exact top-3 per row (cos from raw dots in g_S; diag forced 0);
// ordering = jax.lax.top_k: value desc, index asc on ties.
__device__ __forceinline__ unsigned long long t3key(float v, unsigned j) {
    unsigned u = __float_as_uint(v);
    u = (u & 0x80000000u) ? ~u : (u | 0x80000000u);
    return ((unsigned long long)u << 32) | (0xFFFFFFFFu - j);
}
__global__ void k_top3() {
    int i = blockIdx.x, tid = threadIdx.x; // 256 threads
    float ni = g_hnorm[i];
    const float* Srow = g_S + (size_t)i * NST;
    unsigned long long k0 = 0, k1 = 0, k2 = 0;
    for (int j = tid; j < NST; j += 256) {
        float d = ni * g_hnorm[j];
        float c = (d == 0.f) ? 0.f : Srow[j] / d;
        if (j == i) c = 0.f;                 // eye mask before top_k
        unsigned long long kk = t3key(c, (unsigned)j);
        if (kk > k0) { k2 = k1; k1 = k0; k0 = kk; }
        else if (kk > k1) { k2 = k1; k1 = kk; }
        else if (kk > k2) { k2 = kk; }
    }
    __shared__ unsigned long long red[256];
    __shared__ unsigned long long win[3];
    for (int r = 0; r < 3; r++) {
        red[tid] = k0;
        __syncthreads();
        for (int s = 128; s > 0; s >>= 1) {
            if (tid < s && red[tid + s] > red[tid]) red[tid] = red[tid + s];
            __syncthreads();
        }
        unsigned long long best = red[0];
        __syncthreads();
        if (k0 == best) { k0 = k1; k1 = k2; k2 = 0; }  // keys unique (index bits)
        if (tid == 0) win[r] = best;
        __syncthreads();
    }
    if (tid < 3) {
        unsigned long long key = win[tid];
        unsigned j = 0xFFFFFFFFu - (unsigned)(key & 0xFFFFFFFFu);
        unsigned u = (unsigned)(key >> 32);
        u = (u & 0x80000000u) ? (u ^ 0x80000000u) : ~u;
        g_idx3[i * 3 + tid] = (int)j;
        g_val3[i * 3 + tid] = __uint_as_float(u);
    }
}

// hidden2[idx[i,k],:] += val[i,k]*h_shared[i,:]; colsum[idx] += val
__global__ void k_scatter() {
    int i = blockIdx.x, tid = threadIdx.x; // 128 threads
    float h = g_hshared[(size_t)i * HH + tid];
#pragma unroll
    for (int k = 0; k < 3; k++) {
        int j = g_idx3[i * 3 + k];
        float v = g_val3[i * 3 + k];
        atomicAdd(&g_hidden2[(size_t)j * HH + tid], v * h);
        if (tid == 0) atomicAdd(&g_colsum[j], v);
    }
}

// diagonal re-add (colsum_nz * diag) + keep2 + row norms of hidden2
__global__ void k_diag() {
    int j = blockIdx.x, tid = threadIdx.x; // 128 threads
    float v = g_hidden2[(size_t)j * HH + tid];
    if (g_colsum[j] != 0.f && g_hnorm[j] > 0.f)
        v += g_hshared[(size_t)j * HH + tid];   // diag = cos(h,h) = 1
    g_hidden2[(size_t)j * HH + tid] = v;
    float s = v, q = v * v;
#pragma unroll
    for (int o = 16; o; o >>= 1) {
        s += __shfl_xor_sync(0xffffffffu, s, o);
        q += __shfl_xor_sync(0xffffffffu, q, o);
    }
    __shared__ float ss[4], qq[4];
    int wi = tid >> 5, ln = tid & 31;
    if (!ln) { ss[wi] = s; qq[wi] = q; }
    __syncthreads();
    if (tid == 0) {
        float S = ss[0] + ss[1] + ss[2] + ss[3];
        float Q = qq[0] + qq[1] + qq[2] + qq[3];
        g_keep2[j] = (S != 0.f) ? 1 : 0;
        g_norm2[j] = sqrtf(Q);
    }
}

__global__ void k_sub(const float* __restrict__ x, const float* __restrict__ a,
                      float* __restrict__ o, size_t n) {
    size_t i = (size_t)blockIdx.x * blockDim.x + threadIdx.x;
    size_t st = (size_t)gridDim.x * blockDim.x;
    for (; i < n; i += st) o[i] = x[i] - a[i];
}
__global__ void k_sub2(const float* __restrict__ x, const float* __restrict__ a,
                       const float* __restrict__ b, float* __restrict__ o, size_t n) {
    size_t i = (size_t)blockIdx.x * blockDim.x + threadIdx.x;
    size_t st = (size_t)gridDim.x * blockDim.x;
    for (; i < n; i += st) o[i] = x[i] - a[i] - b[i];
}

// pred[n] = sum_h (out_ps+out_hs+out_indi)[n,h]*W_out[h] + b_out
__global__ void k_final(const float* __restrict__ W, const float* __restrict__ b,
                        float* __restrict__ out) {
    int n = blockIdx.x, tid = threadIdx.x; // 128 threads
    size_t idx = (size_t)n * HH + tid;
    float v = (g_outps[idx] + g_ouths[idx] + g_outindi[idx]) * W[tid];
#pragma unroll
    for (int o = 16; o; o >>= 1) v += __shfl_xor_sync(0xffffffffu, v, o);
    __shared__ float sm[4];
    int wi = tid >> 5, ln = tid & 31;
    if (!ln) sm[wi] = v;
    __syncthreads();
    if (tid == 0) out[n] = sm[0] + sm[1] + sm[2] + sm[3] + b[0];
}

// ---------------- host orchestration ---------------------------------------
#define SYMF(p, s) do { void* _t = nullptr; cudaGetSymbolAddress(&_t, s); p = (float*)_t; } while (0)
#define SYMI(p, s) do { void* _t = nullptr; cudaGetSymbolAddress(&_t, s); p = (int*)_t; } while (0)

extern "C" void kernel_launch(void* const* d_in, const int* in_sizes, int n_in,
                              void* d_out, int out_size) {
    const float* x      = (const float*)d_in[0];
    const float* mv     = (const float*)d_in[1];
    const int*   cm     = (const int*)d_in[2];
    const float* W_ps   = (const float*)d_in[3];
    const float* b_ps   = (const float*)d_in[4];
    const float* W_hs   = (const float*)d_in[5];
    const float* b_hs   = (const float*)d_in[6];
    const float* W_psf  = (const float*)d_in[7];
    const float* b_psf  = (const float*)d_in[8];
    const float* W_hsf  = (const float*)d_in[9];
    const float* b_hsf  = (const float*)d_in[10];
    const float* W_psb  = (const float*)d_in[11];
    const float* b_psb  = (const float*)d_in[12];
    const float* W_hsb  = (const float*)d_in[13];
    const float* b_hsb  = (const float*)d_in[14];
    const float* W_indi = (const float*)d_in[15];
    const float* b_indi = (const float*)d_in[16];
    // d_in[17..22] (W/b_out_ps, W/b_out_hs, W/b_out_indi) are unused by the reference
    const float* W_out  = (const float*)d_in[23];
    const float* b_out  = (const float*)d_in[24];
    float* out = (float*)d_out;

    float *pS, *pL, *ph1, *phB, *pcsmv, *pxn, *pnB, *phn, *pn2, *pcolsum;
    float *pppre, *ppsh, *ppb, *pops, *phs, *ph2, *phip, *phi, *phb2, *pohs, *pind, *poind;
    int *pk1, *pk2;
    SYMF(pS, g_S);        SYMF(pL, g_L);         SYMF(ph1, g_hidden1);  SYMF(phB, g_hiddenB);
    SYMF(pcsmv, g_csmv);  SYMF(pxn, g_xnorm);    SYMF(pnB, g_normB);    SYMF(phn, g_hnorm);
    SYMF(pn2, g_norm2);   SYMF(pcolsum, g_colsum);
    SYMF(pppre, g_ppre);  SYMF(ppsh, g_pshared); SYMF(ppb, g_pback);    SYMF(pops, g_outps);
    SYMF(phs, g_hshared); SYMF(ph2, g_hidden2);  SYMF(phip, g_hinfopre);
    SYMF(phi, g_hinfo);   SYMF(phb2, g_hback);   SYMF(pohs, g_ouths);
    SYMF(pind, g_indiv);  SYMF(poind, g_outindi);
    SYMI(pk1, g_keep1);   SYMI(pk2, g_keep2);

    const size_t NH = (size_t)NST * HH;

    // zero accumulation targets (these are replayed every graph launch)
    kzero<<<8, 256>>>(pcsmv, CC);
    kzero<<<64, 256>>>(phB, (size_t)CC * HH);
    kzero<<<512, 256>>>(pppre, NH);
    kzero<<<512, 256>>>(ph2, NH);
    kzero<<<512, 256>>>(phip, NH);
    kzero<<<32, 256>>>(pcolsum, NST);

    // ---- stage 1: market-value concept aggregation --------------------------
    k_rowstats<<<NST, 128>>>(x, pxn, nullptr);
    k_csmv<<<dim3(CC / 128, 16), 128>>>(cm, mv);
    k_cagg<<<CC, 128>>>(cm, mv, x);
    k_rowstats<<<CC, 128>>>(ph1, nullptr, pk1);                 // keep1

    // ---- stage 2: softmax-over-stocks re-aggregation -------------------------
    gemm128<0, 1><<<dim3(NST / 128, CC / 128, 1), 256>>>(ph1, x, pL, CC, NST, HH,
                                                         nullptr, nullptr, nullptr, nullptr);
    k_rowsoftmax<<<CC, 256, NST * 4>>>(pL, NST);
    gemm128<0, 0><<<dim3(1, CC / 128, 32), 256>>>(pL, x, phB, CC, HH, NST,
                                                  nullptr, nullptr, nullptr, nullptr);
    k_rowstats<<<CC, 128>>>(phB, pnB, nullptr);

    // ---- stage 3: c2s attention -> p branch ---------------------------------
    gemm128<1, 1><<<dim3(CC / 128, NST / 128, 1), 256>>>(x, phB, pL, NST, CC, HH,
                                                         pxn, pnB, pk1, nullptr);
    k_rowsoftmax<<<NST, 256, CC * 4>>>(pL, CC);
    gemm128<0, 0><<<dim3(1, NST / 128, 4), 256>>>(pL, phB, pppre, NST, HH, CC,
                                                  nullptr, nullptr, nullptr, nullptr);
    gemm128<2, 0><<<dim3(1, NST / 128, 1), 256>>>(pppre, W_ps, ppsh, NST, HH, HH,
                                                  nullptr, nullptr, nullptr, b_ps);
    gemm128<2, 0><<<dim3(1, NST / 128, 1), 256>>>(ppsh, W_psb, ppb, NST, HH, HH,
                                                  nullptr, nullptr, nullptr, b_psb);
    gemm128<3, 0><<<dim3(1, NST / 128, 1), 256>>>(ppsh, W_psf, pops, NST, HH, HH,
                                                  nullptr, nullptr, nullptr, b_psf);

    // ---- stage 4: hidden-similarity top-3 graph ------------------------------
    k_sub<<<512, 256>>>(x, ppb, phs, NH);                       // h_shared = x - p_back
    k_rowstats<<<NST, 128>>>(phs, phn, nullptr);
    gemm128<0, 1><<<dim3(NST / 128, NST / 128, 1), 256>>>(phs, phs, pS, NST, NST, HH,
                                                          nullptr, nullptr, nullptr, nullptr);
    k_top3<<<NST, 256>>>();
    k_scatter<<<NST, 128>>>();
    k_diag<<<NST, 128>>>();

    // ---- stage 5: hc2s attention -> h branch ---------------------------------
    gemm128<1, 1><<<dim3(NST / 128, NST / 128, 1), 256>>>(phs, ph2, pS, NST, NST, HH,
                                                          phn, pn2, pk2, nullptr);
    k_rowsoftmax<<<NST, 256, NST * 4>>>(pS, NST);
    gemm128<0, 0><<<dim3(1, NST / 128, 8), 256>>>(pS, ph2, phip, NST, HH, NST,
                                                  nullptr, nullptr, nullptr, nullptr);
    gemm128<2, 0><<<dim3(1, NST / 128, 1), 256>>>(phip, W_hs, phi, NST, HH, HH,
                                                  nullptr, nullptr, nullptr, b_hs);
    gemm128<2, 0><<<dim3(1, NST / 128, 1), 256>>>(phi, W_hsb, phb2, NST, HH, HH,
                                                  nullptr, nullptr, nullptr, b_hsb);
    gemm128<3, 0><<<dim3(1, NST / 128, 1), 256>>>(phi, W_hsf, pohs, NST, HH, HH,
                                                  nullptr, nullptr, nullptr, b_hsf);

    // ---- stage 6: individual branch + head -----------------------------------
    k_sub2<<<512, 256>>>(x, ppb, phb2, pind, NH);               // indiv = x - p_back - h_back
    gemm128<3, 0><<<dim3(1, NST / 128, 1), 256>>>(pind, W_indi, poind, NST, HH, HH,
                                                  nullptr, nullptr, nullptr, b_indi);
    k_final<<<NST, 128>>>(W_out, b_out, out);
}

// round 13
// speedup vs baseline: 1.2530x; 1.2530x over previous
#include <cuda_runtime.h>
#include <math.h>
#include <stdint.h>

#define NST 8192
#define CC  512
#define HH  128

// ---------------- scratch (device globals; no allocation allowed) ----------
__device__ float g_S[(size_t)NST * NST];        // 256 MB score matrix
__device__ float g_L[(size_t)NST * CC];         // logits [C,N] then c2s [N,C]
__device__ float g_hidden1[CC * HH];
__device__ float g_hiddenB[CC * HH];
__device__ float g_csmv[CC];
__device__ float g_xrinv[NST];                  // reciprocal row norms (0 if norm==0)
__device__ float g_rinvB[CC];
__device__ int   g_keep1[CC];
__device__ float g_hrinv[NST];
__device__ float g_rinv2[NST];
__device__ int   g_keep2[NST];
__device__ float g_colsum[NST];
__device__ int   g_idx3[NST * 3];
__device__ float g_val3[NST * 3];
__device__ float g_ppre[(size_t)NST * HH];
__device__ float g_pshared[(size_t)NST * HH];
__device__ float g_pback[(size_t)NST * HH];
__device__ float g_outps[(size_t)NST * HH];
__device__ float g_hshared[(size_t)NST * HH];
__device__ float g_hidden2[(size_t)NST * HH];
__device__ float g_hinfopre[(size_t)NST * HH];
__device__ float g_hinfo[(size_t)NST * HH];
__device__ float g_hback[(size_t)NST * HH];
__device__ float g_ouths[(size_t)NST * HH];
__device__ float g_indiv[(size_t)NST * HH];
__device__ float g_outindi[(size_t)NST * HH];

// ---------------- generic 128x128x8 SGEMM, double-buffered -----------------
// C[M,N] = A[M,K] @ (TRANSB ? B[N,K]^T : B[K,N])
// EPI: 0 plain, 1 cosine (xv * ra * rb, reciprocal norms) + keep-mask(-inf),
//      2 +bias, 3 +bias+leakyrelu(0.01)
// gridDim.z > 1 => split-K partial sums via atomicAdd (EPI 0, C pre-zeroed)
template <int EPI, int TRANSB>
__global__ void __launch_bounds__(256)
gemm128(const float* __restrict__ A, const float* __restrict__ B, float* __restrict__ C,
        int M, int N, int K,
        const float* __restrict__ ra, const float* __restrict__ rb,
        const int* __restrict__ keep, const float* __restrict__ bias)
{
    __shared__ float As[2][8][128];
    __shared__ float Bs[2][8][128];
    const int tid = threadIdx.x;
    const int tx = tid & 15, ty = tid >> 4;
    const int m0 = blockIdx.y * 128, n0 = blockIdx.x * 128;

    const int lr = tid >> 1;          // 0..127 tile row
    const int lk = (tid & 1) * 4;     // 0 or 4  k offset
    const int bkr = tid >> 5;         // 0..7    NN B-load row
    const int bc  = (tid & 31) * 4;   // 0..124  NN B-load col

    float acc[8][8];
#pragma unroll
    for (int i = 0; i < 8; i++)
#pragma unroll
        for (int j = 0; j < 8; j++) acc[i][j] = 0.f;

    const int kper = K / gridDim.z;
    const int kb = blockIdx.z * kper;
    const int kend = kb + kper;

    // prologue: load first K-tile into buffer 0
    {
        float4 av = *(const float4*)(A + (size_t)(m0 + lr) * K + (kb + lk));
        As[0][lk + 0][lr] = av.x; As[0][lk + 1][lr] = av.y;
        As[0][lk + 2][lr] = av.z; As[0][lk + 3][lr] = av.w;
        if (TRANSB) {
            float4 bv = *(const float4*)(B + (size_t)(n0 + lr) * K + (kb + lk));
            Bs[0][lk + 0][lr] = bv.x; Bs[0][lk + 1][lr] = bv.y;
            Bs[0][lk + 2][lr] = bv.z; Bs[0][lk + 3][lr] = bv.w;
        } else {
            float4 bv = *(const float4*)(B + (size_t)(kb + bkr) * N + (n0 + bc));
            *(float4*)(&Bs[0][bkr][bc]) = bv;
        }
    }
    __syncthreads();

    int buf = 0;
    for (int k0 = kb; k0 < kend; k0 += 8) {
        const bool more = (k0 + 8) < kend;
        float4 av2, bv2;
        if (more) {   // issue next-tile LDGs first; latency hidden under FFMAs
            av2 = *(const float4*)(A + (size_t)(m0 + lr) * K + (k0 + 8 + lk));
            if (TRANSB)
                bv2 = *(const float4*)(B + (size_t)(n0 + lr) * K + (k0 + 8 + lk));
            else
                bv2 = *(const float4*)(B + (size_t)(k0 + 8 + bkr) * N + (n0 + bc));
        }
        const float (*Ac)[128] = As[buf];
        const float (*Bc)[128] = Bs[buf];
#pragma unroll
        for (int k = 0; k < 8; k++) {
            float4 a0 = *(const float4*)(&Ac[k][ty * 4]);
            float4 a1 = *(const float4*)(&Ac[k][ty * 4 + 64]);
            float4 b0 = *(const float4*)(&Bc[k][tx * 4]);
            float4 b1 = *(const float4*)(&Bc[k][tx * 4 + 64]);
            float ar[8] = {a0.x, a0.y, a0.z, a0.w, a1.x, a1.y, a1.z, a1.w};
            float br[8] = {b0.x, b0.y, b0.z, b0.w, b1.x, b1.y, b1.z, b1.w};
#pragma unroll
            for (int i = 0; i < 8; i++)
#pragma unroll
                for (int j = 0; j < 8; j++)
                    acc[i][j] = fmaf(ar[i], br[j], acc[i][j]);
        }
        if (more) {
            float (*An)[128] = As[buf ^ 1];
            float (*Bn)[128] = Bs[buf ^ 1];
            An[lk + 0][lr] = av2.x; An[lk + 1][lr] = av2.y;
            An[lk + 2][lr] = av2.z; An[lk + 3][lr] = av2.w;
            if (TRANSB) {
                Bn[lk + 0][lr] = bv2.x; Bn[lk + 1][lr] = bv2.y;
                Bn[lk + 2][lr] = bv2.z; Bn[lk + 3][lr] = bv2.w;
            } else {
                *(float4*)(&Bn[bkr][bc]) = bv2;
            }
            __syncthreads();
            buf ^= 1;
        }
    }

    const bool atom = (gridDim.z > 1);
#pragma unroll
    for (int ih = 0; ih < 2; ih++) {
#pragma unroll
        for (int i = 0; i < 4; i++) {
            const int row = m0 + ih * 64 + ty * 4 + i;
            float nrow = 0.f;
            if (EPI == 1) nrow = ra[row];
#pragma unroll
            for (int jh = 0; jh < 2; jh++) {
                const int cb = n0 + jh * 64 + tx * 4;
                float v[4];
#pragma unroll
                for (int j = 0; j < 4; j++) {
                    float xv = acc[ih * 4 + i][jh * 4 + j];
                    const int col = cb + j;
                    if (EPI == 1) {
                        xv = xv * (nrow * rb[col]);   // rinv==0 encodes denom==0 -> 0
                        if (!keep[col]) xv = __int_as_float(0xff800000); // -inf
                    } else if (EPI == 2) {
                        xv += bias[col];
                    } else if (EPI == 3) {
                        xv += bias[col];
                        xv = xv > 0.f ? xv : 0.01f * xv;
                    }
                    v[j] = xv;
                }
                float* cp = C + (size_t)row * N + cb;
                if (!atom) {
                    float4 o; o.x = v[0]; o.y = v[1]; o.z = v[2]; o.w = v[3];
                    *(float4*)cp = o;
                } else {
                    atomicAdd(cp + 0, v[0]); atomicAdd(cp + 1, v[1]);
                    atomicAdd(cp + 2, v[2]); atomicAdd(cp + 3, v[3]);
                }
            }
        }
    }
}

// ---------------- small kernels --------------------------------------------
__global__ void kzero(float* p, size_t n) {
    size_t i = (size_t)blockIdx.x * blockDim.x + threadIdx.x;
    size_t st = (size_t)gridDim.x * blockDim.x;
    for (; i < n; i += st) p[i] = 0.f;
}

__global__ void k_csmv(const int* __restrict__ cm, const float* __restrict__ mv) {
    int c = blockIdx.x * 128 + threadIdx.x;
    int y = blockIdx.y;
    const int chunk = NST / 16;
    float acc = 0.f;
    for (int n = y * chunk; n < (y + 1) * chunk; ++n)
        acc += (float)cm[(size_t)n * CC + c] * mv[n];
    atomicAdd(&g_csmv[c], acc);
}

// hidden1[c,:] = (1/(csmv[c]+1)) * sum_{n: cm[n,c]=1} mv[n]*x[n,:]
__global__ void k_cagg(const int* __restrict__ cm, const float* __restrict__ mv,
                       const float* __restrict__ x) {
    int c = blockIdx.x, tid = threadIdx.x; // 128 threads over H
    __shared__ float w[128];
    float acc = 0.f;
    for (int n0 = 0; n0 < NST; n0 += 128) {
        int n = n0 + tid;
        w[tid] = (float)cm[(size_t)n * CC + c] * mv[n];
        __syncthreads();
#pragma unroll 8
        for (int nn = 0; nn < 128; nn++) {
            float ww = w[nn];
            if (ww != 0.f) acc = fmaf(ww, x[(size_t)(n0 + nn) * HH + tid], acc);
        }
        __syncthreads();
    }
    g_hidden1[c * HH + tid] = acc / (g_csmv[c] + 1.f);
}

// per-row reciprocal L2 norm (0 when norm==0) and/or nonzero-rowsum flag
__global__ void k_rowstats(const float* __restrict__ X, float* rinv, int* keep) {
    int r = blockIdx.x, tid = threadIdx.x;
    float v = X[(size_t)r * HH + tid];
    float s = v, q = v * v;
#pragma unroll
    for (int o = 16; o; o >>= 1) {
        s += __shfl_xor_sync(0xffffffffu, s, o);
        q += __shfl_xor_sync(0xffffffffu, q, o);
    }
    __shared__ float ss[4], qq[4];
    int wi = tid >> 5, ln = tid & 31;
    if (!ln) { ss[wi] = s; qq[wi] = q; }
    __syncthreads();
    if (tid == 0) {
        float S = ss[0] + ss[1] + ss[2] + ss[3];
        float Q = qq[0] + qq[1] + qq[2] + qq[3];
        if (rinv) {
            float nm = sqrtf(Q);
            rinv[r] = (nm == 0.f) ? 0.f : 1.f / nm;
        }
        if (keep) keep[r] = (S != 0.f) ? 1 : 0;
    }
}

// in-place row softmax; row cached in dynamic smem (cols*4 bytes)
__global__ void k_rowsoftmax(float* __restrict__ X, int cols) {
    extern __shared__ float buf[];
    __shared__ float red[8];
    __shared__ float bc0;
    int r = blockIdx.x, tid = threadIdx.x; // 256 threads
    int wi = tid >> 5, ln = tid & 31;
    float* p = X + (size_t)r * cols;

    float mx = -INFINITY;
    for (int j = tid; j < cols; j += 256) { float v = p[j]; buf[j] = v; mx = fmaxf(mx, v); }
#pragma unroll
    for (int o = 16; o; o >>= 1) mx = fmaxf(mx, __shfl_xor_sync(0xffffffffu, mx, o));
    if (!ln) red[wi] = mx;
    __syncthreads();
    if (tid == 0) {
        float t = red[0];
#pragma unroll
        for (int k = 1; k < 8; k++) t = fmaxf(t, red[k]);
        bc0 = t;
    }
    __syncthreads();
    mx = bc0;

    float s = 0.f;
    for (int j = tid; j < cols; j += 256) { float e = expf(buf[j] - mx); buf[j] = e; s += e; }
#pragma unroll
    for (int o = 16; o; o >>= 1) s += __shfl_xor_sync(0xffffffffu, s, o);
    __syncthreads();
    if (!ln) red[wi] = s;
    __syncthreads();
    if (tid == 0) {
        float t = 0.f;
#pragma unroll
        for (int k = 0; k < 8; k++) t += red[k];
        bc0 = 1.f / t;
    }
    __syncthreads();
    float inv = bc0;
    for (int j = tid; j < cols; j += 256) p[j] = buf[j] * inv;
}

// exact top-3 per row (cos via reciprocal norms; diag forced 0);
// ordering = jax.lax.top_k: value desc, index asc on ties.
__device__ __forceinline__ unsigned long long t3key(float v, unsigned j) {
    unsigned u = __float_as_uint(v);
    u = (u & 0x80000000u) ? ~u : (u | 0x80000000u);
    return ((unsigned long long)u << 32) | (0xFFFFFFFFu - j);
}
__global__ void k_top3() {
    int i = blockIdx.x, tid = threadIdx.x; // 256 threads
    float ri = g_hrinv[i];
    const float* Srow = g_S + (size_t)i * NST;
    unsigned long long k0 = 0, k1 = 0, k2 = 0;
    for (int j = tid; j < NST; j += 256) {
        float c = Srow[j] * (ri * g_hrinv[j]);
        c += 0.f;                            // canonicalize -0 -> +0 (match ref)
        if (j == i) c = 0.f;                 // eye mask before top_k
        unsigned long long kk = t3key(c, (unsigned)j);
        if (kk > k0) { k2 = k1; k1 = k0; k0 = kk; }
        else if (kk > k1) { k2 = k1; k1 = kk; }
        else if (kk > k2) { k2 = kk; }
    }
    __shared__ unsigned long long red[256];
    __shared__ unsigned long long win[3];
    for (int r = 0; r < 3; r++) {
        red[tid] = k0;
        __syncthreads();
        for (int s = 128; s > 0; s >>= 1) {
            if (tid < s && red[tid + s] > red[tid]) red[tid] = red[tid + s];
            __syncthreads();
        }
        unsigned long long best = red[0];
        __syncthreads();
        if (k0 == best) { k0 = k1; k1 = k2; k2 = 0; }  // keys unique (index bits)
        if (tid == 0) win[r] = best;
        __syncthreads();
    }
    if (tid < 3) {
        unsigned long long key = win[tid];
        unsigned j = 0xFFFFFFFFu - (unsigned)(key & 0xFFFFFFFFu);
        unsigned u = (unsigned)(key >> 32);
        u = (u & 0x80000000u) ? (u ^ 0x80000000u) : ~u;
        g_idx3[i * 3 + tid] = (int)j;
        g_val3[i * 3 + tid] = __uint_as_float(u);
    }
}

// hidden2[idx[i,k],:] += val[i,k]*h_shared[i,:]; colsum[idx] += val
__global__ void k_scatter() {
    int i = blockIdx.x, tid = threadIdx.x; // 128 threads
    float h = g_hshared[(size_t)i * HH + tid];
#pragma unroll
    for (int k = 0; k < 3; k++) {
        int j = g_idx3[i * 3 + k];
        float v = g_val3[i * 3 + k];
        atomicAdd(&g_hidden2[(size_t)j * HH + tid], v * h);
        if (tid == 0) atomicAdd(&g_colsum[j], v);
    }
}

// diagonal re-add (colsum_nz * diag) + keep2 + reciprocal norms of hidden2
__global__ void k_diag() {
    int j = blockIdx.x, tid = threadIdx.x; // 128 threads
    float v = g_hidden2[(size_t)j * HH + tid];
    if (g_colsum[j] != 0.f && g_hrinv[j] > 0.f)
        v += g_hshared[(size_t)j * HH + tid];   // diag = cos(h,h) = 1
    g_hidden2[(size_t)j * HH + tid] = v;
    float s = v, q = v * v;
#pragma unroll
    for (int o = 16; o; o >>= 1) {
        s += __shfl_xor_sync(0xffffffffu, s, o);
        q += __shfl_xor_sync(0xffffffffu, q, o);
    }
    __shared__ float ss[4], qq[4];
    int wi = tid >> 5, ln = tid & 31;
    if (!ln) { ss[wi] = s; qq[wi] = q; }
    __syncthreads();
    if (tid == 0) {
        float S = ss[0] + ss[1] + ss[2] + ss[3];
        float Q = qq[0] + qq[1] + qq[2] + qq[3];
        g_keep2[j] = (S != 0.f) ? 1 : 0;
        float nm = sqrtf(Q);
        g_rinv2[j] = (nm == 0.f) ? 0.f : 1.f / nm;
    }
}

__global__ void k_sub(const float* __restrict__ x, const float* __restrict__ a,
                      float* __restrict__ o, size_t n) {
    size_t i = (size_t)blockIdx.x * blockDim.x + threadIdx.x;
    size_t st = (size_t)gridDim.x * blockDim.x;
    for (; i < n; i += st) o[i] = x[i] - a[i];
}
__global__ void k_sub2(const float* __restrict__ x, const float* __restrict__ a,
                       const float* __restrict__ b, float* __restrict__ o, size_t n) {
    size_t i = (size_t)blockIdx.x * blockDim.x + threadIdx.x;
    size_t st = (size_t)gridDim.x * blockDim.x;
    for (; i < n; i += st) o[i] = x[i] - a[i] - b[i];
}

// pred[n] = sum_h (out_ps+out_hs+out_indi)[n,h]*W_out[h] + b_out
__global__ void k_final(const float* __restrict__ W, const float* __restrict__ b,
                        float* __restrict__ out) {
    int n = blockIdx.x, tid = threadIdx.x; // 128 threads
    size_t idx = (size_t)n * HH + tid;
    float v = (g_outps[idx] + g_ouths[idx] + g_outindi[idx]) * W[tid];
#pragma unroll
    for (int o = 16; o; o >>= 1) v += __shfl_xor_sync(0xffffffffu, v, o);
    __shared__ float sm[4];
    int wi = tid >> 5, ln = tid & 31;
    if (!ln) sm[wi] = v;
    __syncthreads();
    if (tid == 0) out[n] = sm[0] + sm[1] + sm[2] + sm[3] + b[0];
}

// ---------------- host orchestration ---------------------------------------
#define SYMF(p, s) do { void* _t = nullptr; cudaGetSymbolAddress(&_t, s); p = (float*)_t; } while (0)
#define SYMI(p, s) do { void* _t = nullptr; cudaGetSymbolAddress(&_t, s); p = (int*)_t; } while (0)

extern "C" void kernel_launch(void* const* d_in, const int* in_sizes, int n_in,
                              void* d_out, int out_size) {
    const float* x      = (const float*)d_in[0];
    const float* mv     = (const float*)d_in[1];
    const int*   cm     = (const int*)d_in[2];
    const float* W_ps   = (const float*)d_in[3];
    const float* b_ps   = (const float*)d_in[4];
    const float* W_hs   = (const float*)d_in[5];
    const float* b_hs   = (const float*)d_in[6];
    const float* W_psf  = (const float*)d_in[7];
    const float* b_psf  = (const float*)d_in[8];
    const float* W_hsf  = (const float*)d_in[9];
    const float* b_hsf  = (const float*)d_in[10];
    const float* W_psb  = (const float*)d_in[11];
    const float* b_psb  = (const float*)d_in[12];
    const float* W_hsb  = (const float*)d_in[13];
    const float* b_hsb  = (const float*)d_in[14];
    const float* W_indi = (const float*)d_in[15];
    const float* b_indi = (const float*)d_in[16];
    // d_in[17..22] (W/b_out_ps, W/b_out_hs, W/b_out_indi) are unused by the reference
    const float* W_out  = (const float*)d_in[23];
    const float* b_out  = (const float*)d_in[24];
    float* out = (float*)d_out;

    float *pS, *pL, *ph1, *phB, *pcsmv, *pxr, *prB, *phr, *pr2, *pcolsum;
    float *pppre, *ppsh, *ppb, *pops, *phs, *ph2, *phip, *phi, *phb2, *pohs, *pind, *poind;
    int *pk1, *pk2;
    SYMF(pS, g_S);        SYMF(pL, g_L);         SYMF(ph1, g_hidden1);  SYMF(phB, g_hiddenB);
    SYMF(pcsmv, g_csmv);  SYMF(pxr, g_xrinv);    SYMF(prB, g_rinvB);    SYMF(phr, g_hrinv);
    SYMF(pr2, g_rinv2);   SYMF(pcolsum, g_colsum);
    SYMF(pppre, g_ppre);  SYMF(ppsh, g_pshared); SYMF(ppb, g_pback);    SYMF(pops, g_outps);
    SYMF(phs, g_hshared); SYMF(ph2, g_hidden2);  SYMF(phip, g_hinfopre);
    SYMF(phi, g_hinfo);   SYMF(phb2, g_hback);   SYMF(pohs, g_ouths);
    SYMF(pind, g_indiv);  SYMF(poind, g_outindi);
    SYMI(pk1, g_keep1);   SYMI(pk2, g_keep2);

    const size_t NH = (size_t)NST * HH;

    // zero accumulation targets (replayed every graph launch)
    kzero<<<8, 256>>>(pcsmv, CC);
    kzero<<<64, 256>>>(phB, (size_t)CC * HH);
    kzero<<<512, 256>>>(pppre, NH);
    kzero<<<512, 256>>>(ph2, NH);
    kzero<<<512, 256>>>(phip, NH);
    kzero<<<32, 256>>>(pcolsum, NST);

    // ---- stage 1: market-value concept aggregation --------------------------
    k_rowstats<<<NST, 128>>>(x, pxr, nullptr);
    k_csmv<<<dim3(CC / 128, 16), 128>>>(cm, mv);
    k_cagg<<<CC, 128>>>(cm, mv, x);
    k_rowstats<<<CC, 128>>>(ph1, nullptr, pk1);                 // keep1

    // ---- stage 2: softmax-over-stocks re-aggregation -------------------------
    gemm128<0, 1><<<dim3(NST / 128, CC / 128, 1), 256>>>(ph1, x, pL, CC, NST, HH,
                                                         nullptr, nullptr, nullptr, nullptr);
    k_rowsoftmax<<<CC, 256, NST * 4>>>(pL, NST);
    gemm128<0, 0><<<dim3(1, CC / 128, 32), 256>>>(pL, x, phB, CC, HH, NST,
                                                  nullptr, nullptr, nullptr, nullptr);
    k_rowstats<<<CC, 128>>>(phB, prB, nullptr);

    // ---- stage 3: c2s attention -> p branch ---------------------------------
    gemm128<1, 1><<<dim3(CC / 128, NST / 128, 1), 256>>>(x, phB, pL, NST, CC, HH,
                                                         pxr, prB, pk1, nullptr);
    k_rowsoftmax<<<NST, 256, CC * 4>>>(pL, CC);
    gemm128<0, 0><<<dim3(1, NST / 128, 4), 256>>>(pL, phB, pppre, NST, HH, CC,
                                                  nullptr, nullptr, nullptr, nullptr);
    gemm128<2, 0><<<dim3(1, NST / 128, 1), 256>>>(pppre, W_ps, ppsh, NST, HH, HH,
                                                  nullptr, nullptr, nullptr, b_ps);
    gemm128<2, 0><<<dim3(1, NST / 128, 1), 256>>>(ppsh, W_psb, ppb, NST, HH, HH,
                                                  nullptr, nullptr, nullptr, b_psb);
    gemm128<3, 0><<<dim3(1, NST / 128, 1), 256>>>(ppsh, W_psf, pops, NST, HH, HH,
                                                  nullptr, nullptr, nullptr, b_psf);

    // ---- stage 4: hidden-similarity top-3 graph ------------------------------
    k_sub<<<512, 256>>>(x, ppb, phs, NH);                       // h_shared = x - p_back
    k_rowstats<<<NST, 128>>>(phs, phr, nullptr);
    gemm128<0, 1><<<dim3(NST / 128, NST / 128, 1), 256>>>(phs, phs, pS, NST, NST, HH,
                                                          nullptr, nullptr, nullptr, nullptr);
    k_top3<<<NST, 256>>>();
    k_scatter<<<NST, 128>>>();
    k_diag<<<NST, 128>>>();

    // ---- stage 5: hc2s attention -> h branch ---------------------------------
    gemm128<1, 1><<<dim3(NST / 128, NST / 128, 1), 256>>>(phs, ph2, pS, NST, NST, HH,
                                                          phr, pr2, pk2, nullptr);
    k_rowsoftmax<<<NST, 256, NST * 4>>>(pS, NST);
    gemm128<0, 0><<<dim3(1, NST / 128, 8), 256>>>(pS, ph2, phip, NST, HH, NST,
                                                  nullptr, nullptr, nullptr, nullptr);
    gemm128<2, 0><<<dim3(1, NST / 128, 1), 256>>>(phip, W_hs, phi, NST, HH, HH,
                                                  nullptr, nullptr, nullptr, b_hs);
    gemm128<2, 0><<<dim3(1, NST / 128, 1), 256>>>(phi, W_hsb, phb2, NST, HH, HH,
                                                  nullptr, nullptr, nullptr, b_hsb);
    gemm128<3, 0><<<dim3(1, NST / 128, 1), 256>>>(phi, W_hsf, pohs, NST, HH, HH,
                                                  nullptr, nullptr, nullptr, b_hsf);

    // ---- stage 6: individual branch + head -----------------------------------
    k_sub2<<<512, 256>>>(x, ppb, phb2, pind, NH);               // indiv = x - p_back - h_back
    gemm128<3, 0><<<dim3(1, NST / 128, 1), 256>>>(pind, W_indi, poind, NST, HH, HH,
                                                  nullptr, nullptr, nullptr, b_indi);
    k_final<<<NST, 128>>>(W_out, b_out, out);
}

// round 15
// speedup vs baseline: 1.6758x; 1.3375x over previous
#include <cuda_runtime.h>
#include <cuda_bf16.h>
#include <math.h>
#include <stdint.h>

#define NST 8192
#define CC  512
#define HH  128

// ---------------- scratch (device globals; no allocation allowed) ----------
__device__ float g_S[(size_t)NST * NST];        // 256 MB score matrix (fp32)
__device__ float g_L[(size_t)NST * CC];
__device__ float g_hidden1[CC * HH];
__device__ float g_hiddenB[CC * HH];
__device__ float g_csmv[CC];
__device__ float g_xrinv[NST];
__device__ float g_rinvB[CC];
__device__ int   g_keep1[CC];
__device__ float g_hrinv[NST];
__device__ float g_rinv2[NST];
__device__ int   g_keep2[NST];
__device__ float g_colsum[NST];
__device__ int   g_idx3[NST * 3];
__device__ float g_val3[NST * 3];
__device__ float g_ppre[(size_t)NST * HH];
__device__ float g_pshared[(size_t)NST * HH];
__device__ float g_pback[(size_t)NST * HH];
__device__ float g_outps[(size_t)NST * HH];
__device__ float g_hshared[(size_t)NST * HH];
__device__ float g_hidden2[(size_t)NST * HH];
__device__ float g_hinfopre[(size_t)NST * HH];
__device__ float g_hinfo[(size_t)NST * HH];
__device__ float g_hback[(size_t)NST * HH];
__device__ float g_ouths[(size_t)NST * HH];
__device__ float g_indiv[(size_t)NST * HH];
__device__ float g_outindi[(size_t)NST * HH];
// bf16 split operands for tensor-core GEMMs
__device__ __nv_bfloat16 g_hsh_hi[(size_t)NST * HH];
__device__ __nv_bfloat16 g_hsh_lo[(size_t)NST * HH];
__device__ __nv_bfloat16 g_h2_hi[(size_t)NST * HH];
__device__ __nv_bfloat16 g_h2_lo[(size_t)NST * HH];
__device__ __nv_bfloat16 g_h2T_hi[(size_t)HH * NST];
__device__ __nv_bfloat16 g_h2T_lo[(size_t)HH * NST];
__device__ __nv_bfloat16 g_Sb_hi[(size_t)NST * NST];  // 128 MB
__device__ __nv_bfloat16 g_Sb_lo[(size_t)NST * NST];  // 128 MB

// ---------------- HMMA bf16x3 GEMM (mma.sync, portable sm_80+) -------------
// C[M,N] = A[M,K] @ Bt[N,K]^T, A/Bt split hi+lo bf16; fp32 accumulate.
// Per pass: hi*hi + hi*lo + lo*hi (lo*lo dropped; ~2^-18 relative).
// EPI: 0 plain fp32 store; 1 cosine(ra,rb)+keep-mask(-inf); 2 atomicAdd (split-K)
#define SM_PITCH 56          // bf16 pitch: 112B rows -> 16B-aligned + conflict-free frags
#define SM_TILE  (128 * SM_PITCH)
#define SM_BYTES (4 * SM_TILE * 2)

__device__ __forceinline__ void mma16816(float* c, const uint32_t* a, const uint32_t* b) {
    asm volatile(
        "mma.sync.aligned.m16n8k16.row.col.f32.bf16.bf16.f32 "
        "{%0,%1,%2,%3}, {%4,%5,%6,%7}, {%8,%9}, {%0,%1,%2,%3};\n"
        : "+f"(c[0]), "+f"(c[1]), "+f"(c[2]), "+f"(c[3])
        : "r"(a[0]), "r"(a[1]), "r"(a[2]), "r"(a[3]), "r"(b[0]), "r"(b[1]));
}

template <int EPI>
__global__ void __launch_bounds__(256)
bmma(const __nv_bfloat16* __restrict__ Ahi, const __nv_bfloat16* __restrict__ Alo, int lda,
     const __nv_bfloat16* __restrict__ Bhi, const __nv_bfloat16* __restrict__ Blo, int ldb,
     float* __restrict__ C, int ldc, int K,
     const float* __restrict__ ra, const float* __restrict__ rb, const int* __restrict__ keep)
{
    extern __shared__ __nv_bfloat16 sm[];
    __nv_bfloat16* sAhi = sm;
    __nv_bfloat16* sAlo = sm + SM_TILE;
    __nv_bfloat16* sBhi = sm + 2 * SM_TILE;
    __nv_bfloat16* sBlo = sm + 3 * SM_TILE;

    const int tid = threadIdx.x, lane = tid & 31, wid = tid >> 5;
    const int wm = wid & 1, wn = wid >> 1;       // 2 x 4 warp grid
    const int grp = lane >> 2, qid = lane & 3;
    const int m0 = blockIdx.y * 128, n0 = blockIdx.x * 128;

    float acc[4][4][4];
#pragma unroll
    for (int i = 0; i < 4; i++)
#pragma unroll
        for (int j = 0; j < 4; j++)
#pragma unroll
            for (int q = 0; q < 4; q++) acc[i][j][q] = 0.f;

    const int ktiles = K / 32;
    const int kper = ktiles / gridDim.z;
    const int kt0 = blockIdx.z * kper;

    for (int t = 0; t < kper; ++t) {
        const int k0 = (kt0 + t) * 32;
        // fill smem tiles: 128 rows x 32 bf16, uint4 (8 bf16) vectors
#pragma unroll
        for (int i = tid; i < 512; i += 256) {
            int r = i >> 2, cv = (i & 3) * 8;
            *(uint4*)(sAhi + r * SM_PITCH + cv) = *(const uint4*)(Ahi + (size_t)(m0 + r) * lda + k0 + cv);
            *(uint4*)(sAlo + r * SM_PITCH + cv) = *(const uint4*)(Alo + (size_t)(m0 + r) * lda + k0 + cv);
            *(uint4*)(sBhi + r * SM_PITCH + cv) = *(const uint4*)(Bhi + (size_t)(n0 + r) * ldb + k0 + cv);
            *(uint4*)(sBlo + r * SM_PITCH + cv) = *(const uint4*)(Blo + (size_t)(n0 + r) * ldb + k0 + cv);
        }
        __syncthreads();

#pragma unroll
        for (int kk = 0; kk < 32; kk += 16) {
            // B fragments (k16 x n8, col-major): b0 = Bt[n][kk+qid*2..+1], b1 = +8
            uint32_t bh[4][2], bl[4][2];
#pragma unroll
            for (int ni = 0; ni < 4; ni++) {
                int bn = wn * 32 + ni * 8 + grp;
                int bc = kk + qid * 2;
                bh[ni][0] = *(const uint32_t*)(sBhi + bn * SM_PITCH + bc);
                bh[ni][1] = *(const uint32_t*)(sBhi + bn * SM_PITCH + bc + 8);
                bl[ni][0] = *(const uint32_t*)(sBlo + bn * SM_PITCH + bc);
                bl[ni][1] = *(const uint32_t*)(sBlo + bn * SM_PITCH + bc + 8);
            }
#pragma unroll
            for (int mi = 0; mi < 4; mi++) {
                const int ar = wm * 64 + mi * 16 + grp;
                const int ac = kk + qid * 2;
                uint32_t a[4];
                // A-hi fragment
                a[0] = *(const uint32_t*)(sAhi + ar * SM_PITCH + ac);
                a[1] = *(const uint32_t*)(sAhi + (ar + 8) * SM_PITCH + ac);
                a[2] = *(const uint32_t*)(sAhi + ar * SM_PITCH + ac + 8);
                a[3] = *(const uint32_t*)(sAhi + (ar + 8) * SM_PITCH + ac + 8);
#pragma unroll
                for (int ni = 0; ni < 4; ni++) mma16816(acc[mi][ni], a, bh[ni]);
#pragma unroll
                for (int ni = 0; ni < 4; ni++) mma16816(acc[mi][ni], a, bl[ni]);
                // A-lo fragment
                a[0] = *(const uint32_t*)(sAlo + ar * SM_PITCH + ac);
                a[1] = *(const uint32_t*)(sAlo + (ar + 8) * SM_PITCH + ac);
                a[2] = *(const uint32_t*)(sAlo + ar * SM_PITCH + ac + 8);
                a[3] = *(const uint32_t*)(sAlo + (ar + 8) * SM_PITCH + ac + 8);
#pragma unroll
                for (int ni = 0; ni < 4; ni++) mma16816(acc[mi][ni], a, bh[ni]);
            }
        }
        __syncthreads();
    }

    // epilogue: c0,c1 -> (row, col..col+1); c2,c3 -> (row+8, col..col+1)
#pragma unroll
    for (int mi = 0; mi < 4; mi++) {
        const int row0 = m0 + wm * 64 + mi * 16 + grp;
        const int row1 = row0 + 8;
        float ra0 = 0.f, ra1 = 0.f;
        if (EPI == 1) { ra0 = ra[row0]; ra1 = ra[row1]; }
#pragma unroll
        for (int ni = 0; ni < 4; ni++) {
            const int col = n0 + wn * 32 + ni * 8 + qid * 2;
            float* c = acc[mi][ni];
            if (EPI == 0) {
                *(float2*)(C + (size_t)row0 * ldc + col) = make_float2(c[0], c[1]);
                *(float2*)(C + (size_t)row1 * ldc + col) = make_float2(c[2], c[3]);
            } else if (EPI == 1) {
                float rb0 = rb[col], rb1 = rb[col + 1];
                int k0m = keep[col], k1m = keep[col + 1];
                float v0 = k0m ? c[0] * (ra0 * rb0) : __int_as_float(0xff800000);
                float v1 = k1m ? c[1] * (ra0 * rb1) : __int_as_float(0xff800000);
                float v2 = k0m ? c[2] * (ra1 * rb0) : __int_as_float(0xff800000);
                float v3 = k1m ? c[3] * (ra1 * rb1) : __int_as_float(0xff800000);
                *(float2*)(C + (size_t)row0 * ldc + col) = make_float2(v0, v1);
                *(float2*)(C + (size_t)row1 * ldc + col) = make_float2(v2, v3);
            } else {
                atomicAdd(C + (size_t)row0 * ldc + col, c[0]);
                atomicAdd(C + (size_t)row0 * ldc + col + 1, c[1]);
                atomicAdd(C + (size_t)row1 * ldc + col, c[2]);
                atomicAdd(C + (size_t)row1 * ldc + col + 1, c[3]);
            }
        }
    }
}

// ---------------- fp32 SGEMM (small GEMMs) ----------------------------------
template <int EPI, int TRANSB>
__global__ void __launch_bounds__(256)
gemm128(const float* __restrict__ A, const float* __restrict__ B, float* __restrict__ C,
        int M, int N, int K,
        const float* __restrict__ ra, const float* __restrict__ rb,
        const int* __restrict__ keep, const float* __restrict__ bias)
{
    __shared__ float As[2][8][128];
    __shared__ float Bs[2][8][128];
    const int tid = threadIdx.x;
    const int tx = tid & 15, ty = tid >> 4;
    const int m0 = blockIdx.y * 128, n0 = blockIdx.x * 128;
    const int lr = tid >> 1, lk = (tid & 1) * 4;
    const int bkr = tid >> 5, bc = (tid & 31) * 4;

    float acc[8][8];
#pragma unroll
    for (int i = 0; i < 8; i++)
#pragma unroll
        for (int j = 0; j < 8; j++) acc[i][j] = 0.f;

    const int kper = K / gridDim.z;
    const int kb = blockIdx.z * kper;
    const int kend = kb + kper;
    {
        float4 av = *(const float4*)(A + (size_t)(m0 + lr) * K + (kb + lk));
        As[0][lk + 0][lr] = av.x; As[0][lk + 1][lr] = av.y;
        As[0][lk + 2][lr] = av.z; As[0][lk + 3][lr] = av.w;
        if (TRANSB) {
            float4 bv = *(const float4*)(B + (size_t)(n0 + lr) * K + (kb + lk));
            Bs[0][lk + 0][lr] = bv.x; Bs[0][lk + 1][lr] = bv.y;
            Bs[0][lk + 2][lr] = bv.z; Bs[0][lk + 3][lr] = bv.w;
        } else {
            float4 bv = *(const float4*)(B + (size_t)(kb + bkr) * N + (n0 + bc));
            *(float4*)(&Bs[0][bkr][bc]) = bv;
        }
    }
    __syncthreads();
    int buf = 0;
    for (int k0 = kb; k0 < kend; k0 += 8) {
        const bool more = (k0 + 8) < kend;
        float4 av2, bv2;
        if (more) {
            av2 = *(const float4*)(A + (size_t)(m0 + lr) * K + (k0 + 8 + lk));
            if (TRANSB) bv2 = *(const float4*)(B + (size_t)(n0 + lr) * K + (k0 + 8 + lk));
            else        bv2 = *(const float4*)(B + (size_t)(k0 + 8 + bkr) * N + (n0 + bc));
        }
        const float (*Ac)[128] = As[buf];
        const float (*Bc)[128] = Bs[buf];
#pragma unroll
        for (int k = 0; k < 8; k++) {
            float4 a0 = *(const float4*)(&Ac[k][ty * 4]);
            float4 a1 = *(const float4*)(&Ac[k][ty * 4 + 64]);
            float4 b0 = *(const float4*)(&Bc[k][tx * 4]);
            float4 b1 = *(const float4*)(&Bc[k][tx * 4 + 64]);
            float ar[8] = {a0.x, a0.y, a0.z, a0.w, a1.x, a1.y, a1.z, a1.w};
            float br[8] = {b0.x, b0.y, b0.z, b0.w, b1.x, b1.y, b1.z, b1.w};
#pragma unroll
            for (int i = 0; i < 8; i++)
#pragma unroll
                for (int j = 0; j < 8; j++)
                    acc[i][j] = fmaf(ar[i], br[j], acc[i][j]);
        }
        if (more) {
            float (*An)[128] = As[buf ^ 1];
            float (*Bn)[128] = Bs[buf ^ 1];
            An[lk + 0][lr] = av2.x; An[lk + 1][lr] = av2.y;
            An[lk + 2][lr] = av2.z; An[lk + 3][lr] = av2.w;
            if (TRANSB) {
                Bn[lk + 0][lr] = bv2.x; Bn[lk + 1][lr] = bv2.y;
                Bn[lk + 2][lr] = bv2.z; Bn[lk + 3][lr] = bv2.w;
            } else {
                *(float4*)(&Bn[bkr][bc]) = bv2;
            }
            __syncthreads();
            buf ^= 1;
        }
    }

    const bool atom = (gridDim.z > 1);
#pragma unroll
    for (int ih = 0; ih < 2; ih++) {
#pragma unroll
        for (int i = 0; i < 4; i++) {
            const int row = m0 + ih * 64 + ty * 4 + i;
            float nrow = 0.f;
            if (EPI == 1) nrow = ra[row];
#pragma unroll
            for (int jh = 0; jh < 2; jh++) {
                const int cb = n0 + jh * 64 + tx * 4;
                float v[4];
#pragma unroll
                for (int j = 0; j < 4; j++) {
                    float xv = acc[ih * 4 + i][jh * 4 + j];
                    const int col = cb + j;
                    if (EPI == 1) {
                        xv = xv * (nrow * rb[col]);
                        if (!keep[col]) xv = __int_as_float(0xff800000);
                    } else if (EPI == 2) {
                        xv += bias[col];
                    } else if (EPI == 3) {
                        xv += bias[col];
                        xv = xv > 0.f ? xv : 0.01f * xv;
                    }
                    v[j] = xv;
                }
                float* cp = C + (size_t)row * N + cb;
                if (!atom) {
                    float4 o; o.x = v[0]; o.y = v[1]; o.z = v[2]; o.w = v[3];
                    *(float4*)cp = o;
                } else {
                    atomicAdd(cp + 0, v[0]); atomicAdd(cp + 1, v[1]);
                    atomicAdd(cp + 2, v[2]); atomicAdd(cp + 3, v[3]);
                }
            }
        }
    }
}

// ---------------- small kernels --------------------------------------------
__global__ void kzero(float* p, size_t n) {
    size_t i = (size_t)blockIdx.x * blockDim.x + threadIdx.x;
    size_t st = (size_t)gridDim.x * blockDim.x;
    for (; i < n; i += st) p[i] = 0.f;
}

__global__ void k_split(const float* __restrict__ in, __nv_bfloat16* __restrict__ hi,
                        __nv_bfloat16* __restrict__ lo, size_t n) {
    size_t i = (size_t)blockIdx.x * blockDim.x + threadIdx.x;
    size_t st = (size_t)gridDim.x * blockDim.x;
    for (; i < n; i += st) {
        float v = in[i];
        __nv_bfloat16 h = __float2bfloat16(v);
        hi[i] = h;
        lo[i] = __float2bfloat16(v - __bfloat162float(h));
    }
}

// hidden2 [NST,HH] -> transposed split [HH,NST]
__global__ void k_splitT(const float* __restrict__ in, __nv_bfloat16* __restrict__ hiT,
                         __nv_bfloat16* __restrict__ loT) {
    int j = blockIdx.x * 256 + threadIdx.x;   // stock
    int h = blockIdx.y;                        // feature
    float v = in[(size_t)j * HH + h];
    __nv_bfloat16 hv = __float2bfloat16(v);
    hiT[(size_t)h * NST + j] = hv;
    loT[(size_t)h * NST + j] = __float2bfloat16(v - __bfloat162float(hv));
}

__global__ void k_csmv(const int* __restrict__ cm, const float* __restrict__ mv) {
    int c = blockIdx.x * 128 + threadIdx.x;
    int y = blockIdx.y;
    const int chunk = NST / 16;
    float acc = 0.f;
    for (int n = y * chunk; n < (y + 1) * chunk; ++n)
        acc += (float)cm[(size_t)n * CC + c] * mv[n];
    atomicAdd(&g_csmv[c], acc);
}

__global__ void k_cagg(const int* __restrict__ cm, const float* __restrict__ mv,
                       const float* __restrict__ x) {
    int c = blockIdx.x, tid = threadIdx.x;
    __shared__ float w[128];
    float acc = 0.f;
    for (int n0 = 0; n0 < NST; n0 += 128) {
        int n = n0 + tid;
        w[tid] = (float)cm[(size_t)n * CC + c] * mv[n];
        __syncthreads();
#pragma unroll 8
        for (int nn = 0; nn < 128; nn++) {
            float ww = w[nn];
            if (ww != 0.f) acc = fmaf(ww, x[(size_t)(n0 + nn) * HH + tid], acc);
        }
        __syncthreads();
    }
    g_hidden1[c * HH + tid] = acc / (g_csmv[c] + 1.f);
}

__global__ void k_rowstats(const float* __restrict__ X, float* rinv, int* keep) {
    int r = blockIdx.x, tid = threadIdx.x;
    float v = X[(size_t)r * HH + tid];
    float s = v, q = v * v;
#pragma unroll
    for (int o = 16; o; o >>= 1) {
        s += __shfl_xor_sync(0xffffffffu, s, o);
        q += __shfl_xor_sync(0xffffffffu, q, o);
    }
    __shared__ float ss[4], qq[4];
    int wi = tid >> 5, ln = tid & 31;
    if (!ln) { ss[wi] = s; qq[wi] = q; }
    __syncthreads();
    if (tid == 0) {
        float S = ss[0] + ss[1] + ss[2] + ss[3];
        float Q = qq[0] + qq[1] + qq[2] + qq[3];
        if (rinv) {
            float nm = sqrtf(Q);
            rinv[r] = (nm == 0.f) ? 0.f : 1.f / nm;
        }
        if (keep) keep[r] = (S != 0.f) ? 1 : 0;
    }
}

__global__ void k_rowsoftmax(float* __restrict__ X, int cols) {
    extern __shared__ float buf[];
    __shared__ float red[8];
    __shared__ float bc0;
    int r = blockIdx.x, tid = threadIdx.x;
    int wi = tid >> 5, ln = tid & 31;
    float* p = X + (size_t)r * cols;
    float mx = -INFINITY;
    for (int j = tid; j < cols; j += 256) { float v = p[j]; buf[j] = v; mx = fmaxf(mx, v); }
#pragma unroll
    for (int o = 16; o; o >>= 1) mx = fmaxf(mx, __shfl_xor_sync(0xffffffffu, mx, o));
    if (!ln) red[wi] = mx;
    __syncthreads();
    if (tid == 0) {
        float t = red[0];
#pragma unroll
        for (int k = 1; k < 8; k++) t = fmaxf(t, red[k]);
        bc0 = t;
    }
    __syncthreads();
    mx = bc0;
    float s = 0.f;
    for (int j = tid; j < cols; j += 256) { float e = expf(buf[j] - mx); buf[j] = e; s += e; }
#pragma unroll
    for (int o = 16; o; o >>= 1) s += __shfl_xor_sync(0xffffffffu, s, o);
    __syncthreads();
    if (!ln) red[wi] = s;
    __syncthreads();
    if (tid == 0) {
        float t = 0.f;
#pragma unroll
        for (int k = 0; k < 8; k++) t += red[k];
        bc0 = 1.f / t;
    }
    __syncthreads();
    float inv = bc0;
    for (int j = tid; j < cols; j += 256) p[j] = buf[j] * inv;
}

// row softmax over S (fp32 in) -> bf16 hi/lo split out
__global__ void k_rowsoftmax_bf16(const float* __restrict__ X,
                                  __nv_bfloat16* __restrict__ hi,
                                  __nv_bfloat16* __restrict__ lo) {
    extern __shared__ float buf[];
    __shared__ float red[8];
    __shared__ float bc0;
    const int cols = NST;
    int r = blockIdx.x, tid = threadIdx.x;
    int wi = tid >> 5, ln = tid & 31;
    const float* p = X + (size_t)r * cols;
    float mx = -INFINITY;
    for (int j = tid; j < cols; j += 256) { float v = p[j]; buf[j] = v; mx = fmaxf(mx, v); }
#pragma unroll
    for (int o = 16; o; o >>= 1) mx = fmaxf(mx, __shfl_xor_sync(0xffffffffu, mx, o));
    if (!ln) red[wi] = mx;
    __syncthreads();
    if (tid == 0) {
        float t = red[0];
#pragma unroll
        for (int k = 1; k < 8; k++) t = fmaxf(t, red[k]);
        bc0 = t;
    }
    __syncthreads();
    mx = bc0;
    float s = 0.f;
    for (int j = tid; j < cols; j += 256) { float e = expf(buf[j] - mx); buf[j] = e; s += e; }
#pragma unroll
    for (int o = 16; o; o >>= 1) s += __shfl_xor_sync(0xffffffffu, s, o);
    __syncthreads();
    if (!ln) red[wi] = s;
    __syncthreads();
    if (tid == 0) {
        float t = 0.f;
#pragma unroll
        for (int k = 0; k < 8; k++) t += red[k];
        bc0 = 1.f / t;
    }
    __syncthreads();
    float inv = bc0;
    for (int j = tid; j < cols; j += 256) {
        float v = buf[j] * inv;
        __nv_bfloat16 h = __float2bfloat16(v);
        hi[(size_t)r * cols + j] = h;
        lo[(size_t)r * cols + j] = __float2bfloat16(v - __bfloat162float(h));
    }
}

__device__ __forceinline__ unsigned long long t3key(float v, unsigned j) {
    unsigned u = __float_as_uint(v);
    u = (u & 0x80000000u) ? ~u : (u | 0x80000000u);
    return ((unsigned long long)u << 32) | (0xFFFFFFFFu - j);
}
__global__ void k_top3() {
    int i = blockIdx.x, tid = threadIdx.x;
    float ri = g_hrinv[i];
    const float* Srow = g_S + (size_t)i * NST;
    unsigned long long k0 = 0, k1 = 0, k2 = 0;
    for (int j = tid; j < NST; j += 256) {
        float c = Srow[j] * (ri * g_hrinv[j]);
        c += 0.f;
        if (j == i) c = 0.f;
        unsigned long long kk = t3key(c, (unsigned)j);
        if (kk > k0) { k2 = k1; k1 = k0; k0 = kk; }
        else if (kk > k1) { k2 = k1; k1 = kk; }
        else if (kk > k2) { k2 = kk; }
    }
    __shared__ unsigned long long red[256];
    __shared__ unsigned long long win[3];
    for (int r = 0; r < 3; r++) {
        red[tid] = k0;
        __syncthreads();
        for (int s = 128; s > 0; s >>= 1) {
            if (tid < s && red[tid + s] > red[tid]) red[tid] = red[tid + s];
            __syncthreads();
        }
        unsigned long long best = red[0];
        __syncthreads();
        if (k0 == best) { k0 = k1; k1 = k2; k2 = 0; }
        if (tid == 0) win[r] = best;
        __syncthreads();
    }
    if (tid < 3) {
        unsigned long long key = win[tid];
        unsigned j = 0xFFFFFFFFu - (unsigned)(key & 0xFFFFFFFFu);
        unsigned u = (unsigned)(key >> 32);
        u = (u & 0x80000000u) ? (u ^ 0x80000000u) : ~u;
        g_idx3[i * 3 + tid] = (int)j;
        g_val3[i * 3 + tid] = __uint_as_float(u);
    }
}

__global__ void k_scatter() {
    int i = blockIdx.x, tid = threadIdx.x;
    float h = g_hshared[(size_t)i * HH + tid];
#pragma unroll
    for (int k = 0; k < 3; k++) {
        int j = g_idx3[i * 3 + k];
        float v = g_val3[i * 3 + k];
        atomicAdd(&g_hidden2[(size_t)j * HH + tid], v * h);
        if (tid == 0) atomicAdd(&g_colsum[j], v);
    }
}

__global__ void k_diag() {
    int j = blockIdx.x, tid = threadIdx.x;
    float v = g_hidden2[(size_t)j * HH + tid];
    if (g_colsum[j] != 0.f && g_hrinv[j] > 0.f)
        v += g_hshared[(size_t)j * HH + tid];
    g_hidden2[(size_t)j * HH + tid] = v;
    float s = v, q = v * v;
#pragma unroll
    for (int o = 16; o; o >>= 1) {
        s += __shfl_xor_sync(0xffffffffu, s, o);
        q += __shfl_xor_sync(0xffffffffu, q, o);
    }
    __shared__ float ss[4], qq[4];
    int wi = tid >> 5, ln = tid & 31;
    if (!ln) { ss[wi] = s; qq[wi] = q; }
    __syncthreads();
    if (tid == 0) {
        float S = ss[0] + ss[1] + ss[2] + ss[3];
        float Q = qq[0] + qq[1] + qq[2] + qq[3];
        g_keep2[j] = (S != 0.f) ? 1 : 0;
        float nm = sqrtf(Q);
        g_rinv2[j] = (nm == 0.f) ? 0.f : 1.f / nm;
    }
}

__global__ void k_sub(const float* __restrict__ x, const float* __restrict__ a,
                      float* __restrict__ o, size_t n) {
    size_t i = (size_t)blockIdx.x * blockDim.x + threadIdx.x;
    size_t st = (size_t)gridDim.x * blockDim.x;
    for (; i < n; i += st) o[i] = x[i] - a[i];
}
__global__ void k_sub2(const float* __restrict__ x, const float* __restrict__ a,
                       const float* __restrict__ b, float* __restrict__ o, size_t n) {
    size_t i = (size_t)blockIdx.x * blockDim.x + threadIdx.x;
    size_t st = (size_t)gridDim.x * blockDim.x;
    for (; i < n; i += st) o[i] = x[i] - a[i] - b[i];
}

__global__ void k_final(const float* __restrict__ W, const float* __restrict__ b,
                        float* __restrict__ out) {
    int n = blockIdx.x, tid = threadIdx.x;
    size_t idx = (size_t)n * HH + tid;
    float v = (g_outps[idx] + g_ouths[idx] + g_outindi[idx]) * W[tid];
#pragma unroll
    for (int o = 16; o; o >>= 1) v += __shfl_xor_sync(0xffffffffu, v, o);
    __shared__ float sm[4];
    int wi = tid >> 5, ln = tid & 31;
    if (!ln) sm[wi] = v;
    __syncthreads();
    if (tid == 0) out[n] = sm[0] + sm[1] + sm[2] + sm[3] + b[0];
}

// ---------------- host orchestration ---------------------------------------
#define SYMF(p, s) do { void* _t = nullptr; cudaGetSymbolAddress(&_t, s); p = (float*)_t; } while (0)
#define SYMI(p, s) do { void* _t = nullptr; cudaGetSymbolAddress(&_t, s); p = (int*)_t; } while (0)
#define SYMB(p, s) do { void* _t = nullptr; cudaGetSymbolAddress(&_t, s); p = (__nv_bfloat16*)_t; } while (0)

extern "C" void kernel_launch(void* const* d_in, const int* in_sizes, int n_in,
                              void* d_out, int out_size) {
    const float* x      = (const float*)d_in[0];
    const float* mv     = (const float*)d_in[1];
    const int*   cm     = (const int*)d_in[2];
    const float* W_ps   = (const float*)d_in[3];
    const float* b_ps   = (const float*)d_in[4];
    const float* W_hs   = (const float*)d_in[5];
    const float* b_hs   = (const float*)d_in[6];
    const float* W_psf  = (const float*)d_in[7];
    const float* b_psf  = (const float*)d_in[8];
    const float* W_hsf  = (const float*)d_in[9];
    const float* b_hsf  = (const float*)d_in[10];
    const float* W_psb  = (const float*)d_in[11];
    const float* b_psb  = (const float*)d_in[12];
    const float* W_hsb  = (const float*)d_in[13];
    const float* b_hsb  = (const float*)d_in[14];
    const float* W_indi = (const float*)d_in[15];
    const float* b_indi = (const float*)d_in[16];
    const float* W_out  = (const float*)d_in[23];
    const float* b_out  = (const float*)d_in[24];
    float* out = (float*)d_out;

    float *pS, *pL, *ph1, *phB, *pcsmv, *pxr, *prB, *phr, *pr2, *pcolsum;
    float *pppre, *ppsh, *ppb, *pops, *phs, *ph2, *phip, *phi, *phb2, *pohs, *pind, *poind;
    int *pk1, *pk2;
    __nv_bfloat16 *hsh_hi, *hsh_lo, *h2_hi, *h2_lo, *h2T_hi, *h2T_lo, *Sb_hi, *Sb_lo;
    SYMF(pS, g_S);        SYMF(pL, g_L);         SYMF(ph1, g_hidden1);  SYMF(phB, g_hiddenB);
    SYMF(pcsmv, g_csmv);  SYMF(pxr, g_xrinv);    SYMF(prB, g_rinvB);    SYMF(phr, g_hrinv);
    SYMF(pr2, g_rinv2);   SYMF(pcolsum, g_colsum);
    SYMF(pppre, g_ppre);  SYMF(ppsh, g_pshared); SYMF(ppb, g_pback);    SYMF(pops, g_outps);
    SYMF(phs, g_hshared); SYMF(ph2, g_hidden2);  SYMF(phip, g_hinfopre);
    SYMF(phi, g_hinfo);   SYMF(phb2, g_hback);   SYMF(pohs, g_ouths);
    SYMF(pind, g_indiv);  SYMF(poind, g_outindi);
    SYMI(pk1, g_keep1);   SYMI(pk2, g_keep2);
    SYMB(hsh_hi, g_hsh_hi); SYMB(hsh_lo, g_hsh_lo);
    SYMB(h2_hi, g_h2_hi);   SYMB(h2_lo, g_h2_lo);
    SYMB(h2T_hi, g_h2T_hi); SYMB(h2T_lo, g_h2T_lo);
    SYMB(Sb_hi, g_Sb_hi);   SYMB(Sb_lo, g_Sb_lo);

    cudaFuncSetAttribute(bmma<0>, cudaFuncAttributeMaxDynamicSharedMemorySize, SM_BYTES);
    cudaFuncSetAttribute(bmma<1>, cudaFuncAttributeMaxDynamicSharedMemorySize, SM_BYTES);
    cudaFuncSetAttribute(bmma<2>, cudaFuncAttributeMaxDynamicSharedMemorySize, SM_BYTES);

    const size_t NH = (size_t)NST * HH;

    // zero accumulation targets
    kzero<<<8, 256>>>(pcsmv, CC);
    kzero<<<64, 256>>>(phB, (size_t)CC * HH);
    kzero<<<512, 256>>>(pppre, NH);
    kzero<<<512, 256>>>(ph2, NH);
    kzero<<<512, 256>>>(phip, NH);
    kzero<<<32, 256>>>(pcolsum, NST);

    // ---- stage 1: market-value concept aggregation --------------------------
    k_rowstats<<<NST, 128>>>(x, pxr, nullptr);
    k_csmv<<<dim3(CC / 128, 16), 128>>>(cm, mv);
    k_cagg<<<CC, 128>>>(cm, mv, x);
    k_rowstats<<<CC, 128>>>(ph1, nullptr, pk1);

    // ---- stage 2: softmax-over-stocks re-aggregation -------------------------
    gemm128<0, 1><<<dim3(NST / 128, CC / 128, 1), 256>>>(ph1, x, pL, CC, NST, HH,
                                                         nullptr, nullptr, nullptr, nullptr);
    k_rowsoftmax<<<CC, 256, NST * 4>>>(pL, NST);
    gemm128<0, 0><<<dim3(1, CC / 128, 32), 256>>>(pL, x, phB, CC, HH, NST,
                                                  nullptr, nullptr, nullptr, nullptr);
    k_rowstats<<<CC, 128>>>(phB, prB, nullptr);

    // ---- stage 3: c2s attention -> p branch ---------------------------------
    gemm128<1, 1><<<dim3(CC / 128, NST / 128, 1), 256>>>(x, phB, pL, NST, CC, HH,
                                                         pxr, prB, pk1, nullptr);
    k_rowsoftmax<<<NST, 256, CC * 4>>>(pL, CC);
    gemm128<0, 0><<<dim3(1, NST / 128, 4), 256>>>(pL, phB, pppre, NST, HH, CC,
                                                  nullptr, nullptr, nullptr, nullptr);
    gemm128<2, 0><<<dim3(1, NST / 128, 1), 256>>>(pppre, W_ps, ppsh, NST, HH, HH,
                                                  nullptr, nullptr, nullptr, b_ps);
    gemm128<2, 0><<<dim3(1, NST / 128, 1), 256>>>(ppsh, W_psb, ppb, NST, HH, HH,
                                                  nullptr, nullptr, nullptr, b_psb);
    gemm128<3, 0><<<dim3(1, NST / 128, 1), 256>>>(ppsh, W_psf, pops, NST, HH, HH,
                                                  nullptr, nullptr, nullptr, b_psf);

    // ---- stage 4: hidden-similarity top-3 graph (HMMA) -----------------------
    k_sub<<<512, 256>>>(x, ppb, phs, NH);
    k_rowstats<<<NST, 128>>>(phs, phr, nullptr);
    k_split<<<512, 256>>>(phs, hsh_hi, hsh_lo, NH);
    bmma<0><<<dim3(64, 64, 1), 256, SM_BYTES>>>(hsh_hi, hsh_lo, HH, hsh_hi, hsh_lo, HH,
                                                pS, NST, HH, nullptr, nullptr, nullptr);
    k_top3<<<NST, 256>>>();
    k_scatter<<<NST, 128>>>();
    k_diag<<<NST, 128>>>();

    // ---- stage 5: hc2s attention -> h branch (HMMA) ---------------------------
    k_split<<<512, 256>>>(ph2, h2_hi, h2_lo, NH);
    k_splitT<<<dim3(NST / 256, HH), 256>>>(ph2, h2T_hi, h2T_lo);
    bmma<1><<<dim3(64, 64, 1), 256, SM_BYTES>>>(hsh_hi, hsh_lo, HH, h2_hi, h2_lo, HH,
                                                pS, NST, HH, phr, pr2, pk2);
    k_rowsoftmax_bf16<<<NST, 256, NST * 4>>>(pS, Sb_hi, Sb_lo);
    bmma<2><<<dim3(1, 64, 8), 256, SM_BYTES>>>(Sb_hi, Sb_lo, NST, h2T_hi, h2T_lo, NST,
                                               phip, HH, NST, nullptr, nullptr, nullptr);
    gemm128<2, 0><<<dim3(1, NST / 128, 1), 256>>>(phip, W_hs, phi, NST, HH, HH,
                                                  nullptr, nullptr, nullptr, b_hs);
    gemm128<2, 0><<<dim3(1, NST / 128, 1), 256>>>(phi, W_hsb, phb2, NST, HH, HH,
                                                  nullptr, nullptr, nullptr, b_hsb);
    gemm128<3, 0><<<dim3(1, NST / 128, 1), 256>>>(phi, W_hsf, pohs, NST, HH, HH,
                                                  nullptr, nullptr, nullptr, b_hsf);

    // ---- stage 6: individual branch + head -----------------------------------
    k_sub2<<<512, 256>>>(x, ppb, phb2, pind, NH);
    gemm128<3, 0><<<dim3(1, NST / 128, 1), 256>>>(pind, W_indi, poind, NST, HH, HH,
                                                  nullptr, nullptr, nullptr, b_indi);
    k_final<<<NST, 128>>>(W_out, b_out, out);
}

// round 16
// speedup vs baseline: 1.6801x; 1.0026x over previous
#include <cuda_runtime.h>
#include <cuda_bf16.h>
#include <math.h>
#include <stdint.h>

#define NST 8192
#define CC  512
#define HH  128

// ---------------- scratch (device globals; no allocation allowed) ----------
__device__ float g_S[(size_t)NST * NST];        // 256 MB score matrix (fp32)
__device__ float g_L[(size_t)NST * CC];
__device__ float g_hidden1[CC * HH];
__device__ float g_hiddenB[CC * HH];
__device__ float g_csmv[CC];
__device__ float g_xrinv[NST];
__device__ float g_rinvB[CC];
__device__ int   g_keep1[CC];
__device__ float g_hrinv[NST];
__device__ float g_rinv2[NST];
__device__ int   g_keep2[NST];
__device__ float g_colsum[NST];
__device__ int   g_idx3[NST * 3];
__device__ float g_val3[NST * 3];
__device__ float g_ppre[(size_t)NST * HH];
__device__ float g_pshared[(size_t)NST * HH];
__device__ float g_pback[(size_t)NST * HH];
__device__ float g_outps[(size_t)NST * HH];
__device__ float g_hshared[(size_t)NST * HH];
__device__ float g_hidden2[(size_t)NST * HH];
__device__ float g_hinfopre[(size_t)NST * HH];
__device__ float g_hinfo[(size_t)NST * HH];
__device__ float g_hback[(size_t)NST * HH];
__device__ float g_ouths[(size_t)NST * HH];
__device__ float g_indiv[(size_t)NST * HH];
__device__ float g_outindi[(size_t)NST * HH];
// bf16 split operands for tensor-core GEMMs
__device__ __nv_bfloat16 g_x_hi[(size_t)NST * HH];
__device__ __nv_bfloat16 g_x_lo[(size_t)NST * HH];
__device__ __nv_bfloat16 g_xT_hi[(size_t)HH * NST];
__device__ __nv_bfloat16 g_xT_lo[(size_t)HH * NST];
__device__ __nv_bfloat16 g_h1_hi[CC * HH];
__device__ __nv_bfloat16 g_h1_lo[CC * HH];
__device__ __nv_bfloat16 g_hB_hi[CC * HH];
__device__ __nv_bfloat16 g_hB_lo[CC * HH];
__device__ __nv_bfloat16 g_hBT_hi[HH * CC];
__device__ __nv_bfloat16 g_hBT_lo[HH * CC];
__device__ __nv_bfloat16 g_Lb_hi[(size_t)NST * CC];
__device__ __nv_bfloat16 g_Lb_lo[(size_t)NST * CC];
__device__ __nv_bfloat16 g_hsh_hi[(size_t)NST * HH];
__device__ __nv_bfloat16 g_hsh_lo[(size_t)NST * HH];
__device__ __nv_bfloat16 g_h2_hi[(size_t)NST * HH];
__device__ __nv_bfloat16 g_h2_lo[(size_t)NST * HH];
__device__ __nv_bfloat16 g_h2T_hi[(size_t)HH * NST];
__device__ __nv_bfloat16 g_h2T_lo[(size_t)HH * NST];
__device__ __nv_bfloat16 g_Sb_hi[(size_t)NST * NST];  // 128 MB
__device__ __nv_bfloat16 g_Sb_lo[(size_t)NST * NST];  // 128 MB

// ---------------- HMMA bf16x3 GEMM (mma.sync, portable sm_80+) -------------
// C[M,N] = A[M,K] @ Bt[N,K]^T, A/Bt split hi+lo bf16; fp32 accumulate.
// Passes: hi*hi + hi*lo + lo*hi (lo*lo dropped; ~2^-18 relative).
// EPI: 0 plain store; 1 cosine(ra,rb)+keep-mask(-inf); 2 atomicAdd (split-K);
//      3 cosine(ra,rb) only
#define SM_PITCH 56
#define SM_TILE  (128 * SM_PITCH)
#define SM_BYTES (4 * SM_TILE * 2)

__device__ __forceinline__ void mma16816(float* c, const uint32_t* a, const uint32_t* b) {
    asm volatile(
        "mma.sync.aligned.m16n8k16.row.col.f32.bf16.bf16.f32 "
        "{%0,%1,%2,%3}, {%4,%5,%6,%7}, {%8,%9}, {%0,%1,%2,%3};\n"
        : "+f"(c[0]), "+f"(c[1]), "+f"(c[2]), "+f"(c[3])
        : "r"(a[0]), "r"(a[1]), "r"(a[2]), "r"(a[3]), "r"(b[0]), "r"(b[1]));
}

template <int EPI>
__global__ void __launch_bounds__(256)
bmma(const __nv_bfloat16* __restrict__ Ahi, const __nv_bfloat16* __restrict__ Alo, int lda,
     const __nv_bfloat16* __restrict__ Bhi, const __nv_bfloat16* __restrict__ Blo, int ldb,
     float* __restrict__ C, int ldc, int K,
     const float* __restrict__ ra, const float* __restrict__ rb, const int* __restrict__ keep)
{
    extern __shared__ __nv_bfloat16 sm[];
    __nv_bfloat16* sAhi = sm;
    __nv_bfloat16* sAlo = sm + SM_TILE;
    __nv_bfloat16* sBhi = sm + 2 * SM_TILE;
    __nv_bfloat16* sBlo = sm + 3 * SM_TILE;

    const int tid = threadIdx.x, lane = tid & 31, wid = tid >> 5;
    const int wm = wid & 1, wn = wid >> 1;
    const int grp = lane >> 2, qid = lane & 3;
    const int m0 = blockIdx.y * 128, n0 = blockIdx.x * 128;

    float acc[4][4][4];
#pragma unroll
    for (int i = 0; i < 4; i++)
#pragma unroll
        for (int j = 0; j < 4; j++)
#pragma unroll
            for (int q = 0; q < 4; q++) acc[i][j][q] = 0.f;

    const int ktiles = K / 32;
    const int kper = ktiles / gridDim.z;
    const int kt0 = blockIdx.z * kper;

    for (int t = 0; t < kper; ++t) {
        const int k0 = (kt0 + t) * 32;
#pragma unroll
        for (int i = tid; i < 512; i += 256) {
            int r = i >> 2, cv = (i & 3) * 8;
            *(uint4*)(sAhi + r * SM_PITCH + cv) = *(const uint4*)(Ahi + (size_t)(m0 + r) * lda + k0 + cv);
            *(uint4*)(sAlo + r * SM_PITCH + cv) = *(const uint4*)(Alo + (size_t)(m0 + r) * lda + k0 + cv);
            *(uint4*)(sBhi + r * SM_PITCH + cv) = *(const uint4*)(Bhi + (size_t)(n0 + r) * ldb + k0 + cv);
            *(uint4*)(sBlo + r * SM_PITCH + cv) = *(const uint4*)(Blo + (size_t)(n0 + r) * ldb + k0 + cv);
        }
        __syncthreads();

#pragma unroll
        for (int kk = 0; kk < 32; kk += 16) {
            uint32_t bh[4][2], bl[4][2];
#pragma unroll
            for (int ni = 0; ni < 4; ni++) {
                int bn = wn * 32 + ni * 8 + grp;
                int bc = kk + qid * 2;
                bh[ni][0] = *(const uint32_t*)(sBhi + bn * SM_PITCH + bc);
                bh[ni][1] = *(const uint32_t*)(sBhi + bn * SM_PITCH + bc + 8);
                bl[ni][0] = *(const uint32_t*)(sBlo + bn * SM_PITCH + bc);
                bl[ni][1] = *(const uint32_t*)(sBlo + bn * SM_PITCH + bc + 8);
            }
#pragma unroll
            for (int mi = 0; mi < 4; mi++) {
                const int ar = wm * 64 + mi * 16 + grp;
                const int ac = kk + qid * 2;
                uint32_t a[4];
                a[0] = *(const uint32_t*)(sAhi + ar * SM_PITCH + ac);
                a[1] = *(const uint32_t*)(sAhi + (ar + 8) * SM_PITCH + ac);
                a[2] = *(const uint32_t*)(sAhi + ar * SM_PITCH + ac + 8);
                a[3] = *(const uint32_t*)(sAhi + (ar + 8) * SM_PITCH + ac + 8);
#pragma unroll
                for (int ni = 0; ni < 4; ni++) mma16816(acc[mi][ni], a, bh[ni]);
#pragma unroll
                for (int ni = 0; ni < 4; ni++) mma16816(acc[mi][ni], a, bl[ni]);
                a[0] = *(const uint32_t*)(sAlo + ar * SM_PITCH + ac);
                a[1] = *(const uint32_t*)(sAlo + (ar + 8) * SM_PITCH + ac);
                a[2] = *(const uint32_t*)(sAlo + ar * SM_PITCH + ac + 8);
                a[3] = *(const uint32_t*)(sAlo + (ar + 8) * SM_PITCH + ac + 8);
#pragma unroll
                for (int ni = 0; ni < 4; ni++) mma16816(acc[mi][ni], a, bh[ni]);
            }
        }
        __syncthreads();
    }

#pragma unroll
    for (int mi = 0; mi < 4; mi++) {
        const int row0 = m0 + wm * 64 + mi * 16 + grp;
        const int row1 = row0 + 8;
        float ra0 = 0.f, ra1 = 0.f;
        if (EPI == 1 || EPI == 3) { ra0 = ra[row0]; ra1 = ra[row1]; }
#pragma unroll
        for (int ni = 0; ni < 4; ni++) {
            const int col = n0 + wn * 32 + ni * 8 + qid * 2;
            float* c = acc[mi][ni];
            if (EPI == 0) {
                *(float2*)(C + (size_t)row0 * ldc + col) = make_float2(c[0], c[1]);
                *(float2*)(C + (size_t)row1 * ldc + col) = make_float2(c[2], c[3]);
            } else if (EPI == 1) {
                float rb0 = rb[col], rb1 = rb[col + 1];
                int k0m = keep[col], k1m = keep[col + 1];
                float v0 = k0m ? c[0] * (ra0 * rb0) : __int_as_float(0xff800000);
                float v1 = k1m ? c[1] * (ra0 * rb1) : __int_as_float(0xff800000);
                float v2 = k0m ? c[2] * (ra1 * rb0) : __int_as_float(0xff800000);
                float v3 = k1m ? c[3] * (ra1 * rb1) : __int_as_float(0xff800000);
                *(float2*)(C + (size_t)row0 * ldc + col) = make_float2(v0, v1);
                *(float2*)(C + (size_t)row1 * ldc + col) = make_float2(v2, v3);
            } else if (EPI == 3) {
                float rb0 = rb[col], rb1 = rb[col + 1];
                *(float2*)(C + (size_t)row0 * ldc + col) =
                    make_float2(c[0] * (ra0 * rb0), c[1] * (ra0 * rb1));
                *(float2*)(C + (size_t)row1 * ldc + col) =
                    make_float2(c[2] * (ra1 * rb0), c[3] * (ra1 * rb1));
            } else {
                atomicAdd(C + (size_t)row0 * ldc + col, c[0]);
                atomicAdd(C + (size_t)row0 * ldc + col + 1, c[1]);
                atomicAdd(C + (size_t)row1 * ldc + col, c[2]);
                atomicAdd(C + (size_t)row1 * ldc + col + 1, c[3]);
            }
        }
    }
}

// ---------------- fp32 SGEMM (H x H linears only) ---------------------------
// EPI: 2 +bias, 3 +bias+leakyrelu(0.01)
template <int EPI>
__global__ void __launch_bounds__(256)
gemm128(const float* __restrict__ A, const float* __restrict__ B, float* __restrict__ C,
        int M, int N, int K, const float* __restrict__ bias)
{
    __shared__ float As[2][8][128];
    __shared__ float Bs[2][8][128];
    const int tid = threadIdx.x;
    const int tx = tid & 15, ty = tid >> 4;
    const int m0 = blockIdx.y * 128, n0 = blockIdx.x * 128;
    const int lr = tid >> 1, lk = (tid & 1) * 4;
    const int bkr = tid >> 5, bc = (tid & 31) * 4;

    float acc[8][8];
#pragma unroll
    for (int i = 0; i < 8; i++)
#pragma unroll
        for (int j = 0; j < 8; j++) acc[i][j] = 0.f;

    {
        float4 av = *(const float4*)(A + (size_t)(m0 + lr) * K + lk);
        As[0][lk + 0][lr] = av.x; As[0][lk + 1][lr] = av.y;
        As[0][lk + 2][lr] = av.z; As[0][lk + 3][lr] = av.w;
        float4 bv = *(const float4*)(B + (size_t)bkr * N + (n0 + bc));
        *(float4*)(&Bs[0][bkr][bc]) = bv;
    }
    __syncthreads();
    int buf = 0;
    for (int k0 = 0; k0 < K; k0 += 8) {
        const bool more = (k0 + 8) < K;
        float4 av2, bv2;
        if (more) {
            av2 = *(const float4*)(A + (size_t)(m0 + lr) * K + (k0 + 8 + lk));
            bv2 = *(const float4*)(B + (size_t)(k0 + 8 + bkr) * N + (n0 + bc));
        }
        const float (*Ac)[128] = As[buf];
        const float (*Bc)[128] = Bs[buf];
#pragma unroll
        for (int k = 0; k < 8; k++) {
            float4 a0 = *(const float4*)(&Ac[k][ty * 4]);
            float4 a1 = *(const float4*)(&Ac[k][ty * 4 + 64]);
            float4 b0 = *(const float4*)(&Bc[k][tx * 4]);
            float4 b1 = *(const float4*)(&Bc[k][tx * 4 + 64]);
            float ar[8] = {a0.x, a0.y, a0.z, a0.w, a1.x, a1.y, a1.z, a1.w};
            float br[8] = {b0.x, b0.y, b0.z, b0.w, b1.x, b1.y, b1.z, b1.w};
#pragma unroll
            for (int i = 0; i < 8; i++)
#pragma unroll
                for (int j = 0; j < 8; j++)
                    acc[i][j] = fmaf(ar[i], br[j], acc[i][j]);
        }
        if (more) {
            float (*An)[128] = As[buf ^ 1];
            float (*Bn)[128] = Bs[buf ^ 1];
            An[lk + 0][lr] = av2.x; An[lk + 1][lr] = av2.y;
            An[lk + 2][lr] = av2.z; An[lk + 3][lr] = av2.w;
            *(float4*)(&Bn[bkr][bc]) = bv2;
            __syncthreads();
            buf ^= 1;
        }
    }

#pragma unroll
    for (int ih = 0; ih < 2; ih++) {
#pragma unroll
        for (int i = 0; i < 4; i++) {
            const int row = m0 + ih * 64 + ty * 4 + i;
#pragma unroll
            for (int jh = 0; jh < 2; jh++) {
                const int cb = n0 + jh * 64 + tx * 4;
                float v[4];
#pragma unroll
                for (int j = 0; j < 4; j++) {
                    float xv = acc[ih * 4 + i][jh * 4 + j] + bias[cb + j];
                    if (EPI == 3) xv = xv > 0.f ? xv : 0.01f * xv;
                    v[j] = xv;
                }
                float4 o; o.x = v[0]; o.y = v[1]; o.z = v[2]; o.w = v[3];
                *(float4*)(C + (size_t)row * N + cb) = o;
            }
        }
    }
}

// ---------------- small kernels --------------------------------------------
__global__ void kzero(float* p, size_t n) {
    size_t i = (size_t)blockIdx.x * blockDim.x + threadIdx.x;
    size_t st = (size_t)gridDim.x * blockDim.x;
    for (; i < n; i += st) p[i] = 0.f;
}

__global__ void k_split(const float* __restrict__ in, __nv_bfloat16* __restrict__ hi,
                        __nv_bfloat16* __restrict__ lo, size_t n) {
    size_t i = (size_t)blockIdx.x * blockDim.x + threadIdx.x;
    size_t st = (size_t)gridDim.x * blockDim.x;
    for (; i < n; i += st) {
        float v = in[i];
        __nv_bfloat16 h = __float2bfloat16(v);
        hi[i] = h;
        lo[i] = __float2bfloat16(v - __bfloat162float(h));
    }
}

// transposed split: in [R, C] -> out [C, R]; grid (R/256, C), 256 threads
__global__ void k_splitT(const float* __restrict__ in, __nv_bfloat16* __restrict__ hiT,
                         __nv_bfloat16* __restrict__ loT, int R, int C) {
    int j = blockIdx.x * 256 + threadIdx.x;
    int h = blockIdx.y;
    float v = in[(size_t)j * C + h];
    __nv_bfloat16 hv = __float2bfloat16(v);
    hiT[(size_t)h * R + j] = hv;
    loT[(size_t)h * R + j] = __float2bfloat16(v - __bfloat162float(hv));
}

__global__ void k_csmv(const int* __restrict__ cm, const float* __restrict__ mv) {
    int c = blockIdx.x * 128 + threadIdx.x;
    int y = blockIdx.y;
    const int chunk = NST / 16;
    float acc = 0.f;
    for (int n = y * chunk; n < (y + 1) * chunk; ++n)
        acc += (float)cm[(size_t)n * CC + c] * mv[n];
    atomicAdd(&g_csmv[c], acc);
}

__global__ void k_cagg(const int* __restrict__ cm, const float* __restrict__ mv,
                       const float* __restrict__ x) {
    int c = blockIdx.x, tid = threadIdx.x;
    __shared__ float w[128];
    float acc = 0.f;
    for (int n0 = 0; n0 < NST; n0 += 128) {
        int n = n0 + tid;
        w[tid] = (float)cm[(size_t)n * CC + c] * mv[n];
        __syncthreads();
#pragma unroll 8
        for (int nn = 0; nn < 128; nn++) {
            float ww = w[nn];
            if (ww != 0.f) acc = fmaf(ww, x[(size_t)(n0 + nn) * HH + tid], acc);
        }
        __syncthreads();
    }
    g_hidden1[c * HH + tid] = acc / (g_csmv[c] + 1.f);
}

__global__ void k_rowstats(const float* __restrict__ X, float* rinv, int* keep) {
    int r = blockIdx.x, tid = threadIdx.x;
    float v = X[(size_t)r * HH + tid];
    float s = v, q = v * v;
#pragma unroll
    for (int o = 16; o; o >>= 1) {
        s += __shfl_xor_sync(0xffffffffu, s, o);
        q += __shfl_xor_sync(0xffffffffu, q, o);
    }
    __shared__ float ss[4], qq[4];
    int wi = tid >> 5, ln = tid & 31;
    if (!ln) { ss[wi] = s; qq[wi] = q; }
    __syncthreads();
    if (tid == 0) {
        float S = ss[0] + ss[1] + ss[2] + ss[3];
        float Q = qq[0] + qq[1] + qq[2] + qq[3];
        if (rinv) {
            float nm = sqrtf(Q);
            rinv[r] = (nm == 0.f) ? 0.f : 1.f / nm;
        }
        if (keep) keep[r] = (S != 0.f) ? 1 : 0;
    }
}

// row softmax (fp32 in) -> bf16 hi/lo split out. SKIPMAX=1 when inputs bounded.
template <int SKIPMAX>
__global__ void k_rowsoftmax_split(const float* __restrict__ X,
                                   __nv_bfloat16* __restrict__ hi,
                                   __nv_bfloat16* __restrict__ lo, int cols) {
    extern __shared__ float buf[];
    __shared__ float red[8];
    __shared__ float bc0;
    int r = blockIdx.x, tid = threadIdx.x;
    int wi = tid >> 5, ln = tid & 31;
    const float* p = X + (size_t)r * cols;

    float mx = 0.f;
    if (!SKIPMAX) {
        float m = -INFINITY;
        for (int j = tid; j < cols; j += 256) { float v = p[j]; buf[j] = v; m = fmaxf(m, v); }
#pragma unroll
        for (int o = 16; o; o >>= 1) m = fmaxf(m, __shfl_xor_sync(0xffffffffu, m, o));
        if (!ln) red[wi] = m;
        __syncthreads();
        if (tid == 0) {
            float t = red[0];
#pragma unroll
            for (int k = 1; k < 8; k++) t = fmaxf(t, red[k]);
            bc0 = t;
        }
        __syncthreads();
        mx = bc0;
        __syncthreads();
    }

    float s = 0.f;
    if (SKIPMAX) {
        for (int j = tid; j < cols; j += 256) { float e = expf(p[j]); buf[j] = e; s += e; }
    } else {
        for (int j = tid; j < cols; j += 256) { float e = expf(buf[j] - mx); buf[j] = e; s += e; }
    }
#pragma unroll
    for (int o = 16; o; o >>= 1) s += __shfl_xor_sync(0xffffffffu, s, o);
    __syncthreads();
    if (!ln) red[wi] = s;
    __syncthreads();
    if (tid == 0) {
        float t = 0.f;
#pragma unroll
        for (int k = 0; k < 8; k++) t += red[k];
        bc0 = 1.f / t;
    }
    __syncthreads();
    float inv = bc0;
    for (int j = tid; j < cols; j += 256) {
        float v = buf[j] * inv;
        __nv_bfloat16 h = __float2bfloat16(v);
        hi[(size_t)r * cols + j] = h;
        lo[(size_t)r * cols + j] = __float2bfloat16(v - __bfloat162float(h));
    }
}

// exact top-3 per row of the COS matrix (g_S already normalized; diag forced 0);
// ordering = jax.lax.top_k: value desc, index asc on ties.
__device__ __forceinline__ unsigned long long t3key(float v, unsigned j) {
    unsigned u = __float_as_uint(v);
    u = (u & 0x80000000u) ? ~u : (u | 0x80000000u);
    return ((unsigned long long)u << 32) | (0xFFFFFFFFu - j);
}
__global__ void k_top3() {
    int i = blockIdx.x, tid = threadIdx.x;
    const float* Srow = g_S + (size_t)i * NST;
    unsigned long long k0 = 0, k1 = 0, k2 = 0;
    for (int j = tid; j < NST; j += 256) {
        float c = Srow[j] + 0.f;             // canonicalize -0 -> +0
        if (j == i) c = 0.f;                 // eye mask before top_k
        unsigned long long kk = t3key(c, (unsigned)j);
        if (kk > k2) {                       // rarely taken after warmup
            if (kk > k1) {
                k2 = k1;
                if (kk > k0) { k1 = k0; k0 = kk; } else k1 = kk;
            } else k2 = kk;
        }
    }
    __shared__ unsigned long long red[256];
    __shared__ unsigned long long win[3];
    for (int r = 0; r < 3; r++) {
        red[tid] = k0;
        __syncthreads();
        for (int s = 128; s > 0; s >>= 1) {
            if (tid < s && red[tid + s] > red[tid]) red[tid] = red[tid + s];
            __syncthreads();
        }
        unsigned long long best = red[0];
        __syncthreads();
        if (k0 == best) { k0 = k1; k1 = k2; k2 = 0; }
        if (tid == 0) win[r] = best;
        __syncthreads();
    }
    if (tid < 3) {
        unsigned long long key = win[tid];
        unsigned j = 0xFFFFFFFFu - (unsigned)(key & 0xFFFFFFFFu);
        unsigned u = (unsigned)(key >> 32);
        u = (u & 0x80000000u) ? (u ^ 0x80000000u) : ~u;
        g_idx3[i * 3 + tid] = (int)j;
        g_val3[i * 3 + tid] = __uint_as_float(u);
    }
}

__global__ void k_scatter() {
    int i = blockIdx.x, tid = threadIdx.x;
    float h = g_hshared[(size_t)i * HH + tid];
#pragma unroll
    for (int k = 0; k < 3; k++) {
        int j = g_idx3[i * 3 + k];
        float v = g_val3[i * 3 + k];
        atomicAdd(&g_hidden2[(size_t)j * HH + tid], v * h);
        if (tid == 0) atomicAdd(&g_colsum[j], v);
    }
}

__global__ void k_diag() {
    int j = blockIdx.x, tid = threadIdx.x;
    float v = g_hidden2[(size_t)j * HH + tid];
    if (g_colsum[j] != 0.f && g_hrinv[j] > 0.f)
        v += g_hshared[(size_t)j * HH + tid];
    g_hidden2[(size_t)j * HH + tid] = v;
    float s = v, q = v * v;
#pragma unroll
    for (int o = 16; o; o >>= 1) {
        s += __shfl_xor_sync(0xffffffffu, s, o);
        q += __shfl_xor_sync(0xffffffffu, q, o);
    }
    __shared__ float ss[4], qq[4];
    int wi = tid >> 5, ln = tid & 31;
    if (!ln) { ss[wi] = s; qq[wi] = q; }
    __syncthreads();
    if (tid == 0) {
        float S = ss[0] + ss[1] + ss[2] + ss[3];
        float Q = qq[0] + qq[1] + qq[2] + qq[3];
        g_keep2[j] = (S != 0.f) ? 1 : 0;
        float nm = sqrtf(Q);
        g_rinv2[j] = (nm == 0.f) ? 0.f : 1.f / nm;
    }
}

__global__ void k_sub(const float* __restrict__ x, const float* __restrict__ a,
                      float* __restrict__ o, size_t n) {
    size_t i = (size_t)blockIdx.x * blockDim.x + threadIdx.x;
    size_t st = (size_t)gridDim.x * blockDim.x;
    for (; i < n; i += st) o[i] = x[i] - a[i];
}
__global__ void k_sub2(const float* __restrict__ x, const float* __restrict__ a,
                       const float* __restrict__ b, float* __restrict__ o, size_t n) {
    size_t i = (size_t)blockIdx.x * blockDim.x + threadIdx.x;
    size_t st = (size_t)gridDim.x * blockDim.x;
    for (; i < n; i += st) o[i] = x[i] - a[i] - b[i];
}

__global__ void k_final(const float* __restrict__ W, const float* __restrict__ b,
                        float* __restrict__ out) {
    int n = blockIdx.x, tid = threadIdx.x;
    size_t idx = (size_t)n * HH + tid;
    float v = (g_outps[idx] + g_ouths[idx] + g_outindi[idx]) * W[tid];
#pragma unroll
    for (int o = 16; o; o >>= 1) v += __shfl_xor_sync(0xffffffffu, v, o);
    __shared__ float sm[4];
    int wi = tid >> 5, ln = tid & 31;
    if (!ln) sm[wi] = v;
    __syncthreads();
    if (tid == 0) out[n] = sm[0] + sm[1] + sm[2] + sm[3] + b[0];
}

// ---------------- host orchestration ---------------------------------------
#define SYMF(p, s) do { void* _t = nullptr; cudaGetSymbolAddress(&_t, s); p = (float*)_t; } while (0)
#define SYMI(p, s) do { void* _t = nullptr; cudaGetSymbolAddress(&_t, s); p = (int*)_t; } while (0)
#define SYMB(p, s) do { void* _t = nullptr; cudaGetSymbolAddress(&_t, s); p = (__nv_bfloat16*)_t; } while (0)

extern "C" void kernel_launch(void* const* d_in, const int* in_sizes, int n_in,
                              void* d_out, int out_size) {
    const float* x      = (const float*)d_in[0];
    const float* mv     = (const float*)d_in[1];
    const int*   cm     = (const int*)d_in[2];
    const float* W_ps   = (const float*)d_in[3];
    const float* b_ps   = (const float*)d_in[4];
    const float* W_hs   = (const float*)d_in[5];
    const float* b_hs   = (const float*)d_in[6];
    const float* W_psf  = (const float*)d_in[7];
    const float* b_psf  = (const float*)d_in[8];
    const float* W_hsf  = (const float*)d_in[9];
    const float* b_hsf  = (const float*)d_in[10];
    const float* W_psb  = (const float*)d_in[11];
    const float* b_psb  = (const float*)d_in[12];
    const float* W_hsb  = (const float*)d_in[13];
    const float* b_hsb  = (const float*)d_in[14];
    const float* W_indi = (const float*)d_in[15];
    const float* b_indi = (const float*)d_in[16];
    const float* W_out  = (const float*)d_in[23];
    const float* b_out  = (const float*)d_in[24];
    float* out = (float*)d_out;

    float *pS, *pL, *ph1, *phB, *pcsmv, *pxr, *prB, *phr, *pr2, *pcolsum;
    float *pppre, *ppsh, *ppb, *pops, *phs, *ph2, *phip, *phi, *phb2, *pohs, *pind, *poind;
    int *pk1, *pk2;
    __nv_bfloat16 *x_hi, *x_lo, *xT_hi, *xT_lo, *h1_hi, *h1_lo, *hB_hi, *hB_lo;
    __nv_bfloat16 *hBT_hi, *hBT_lo, *Lb_hi, *Lb_lo;
    __nv_bfloat16 *hsh_hi, *hsh_lo, *h2_hi, *h2_lo, *h2T_hi, *h2T_lo, *Sb_hi, *Sb_lo;
    SYMF(pS, g_S);        SYMF(pL, g_L);         SYMF(ph1, g_hidden1);  SYMF(phB, g_hiddenB);
    SYMF(pcsmv, g_csmv);  SYMF(pxr, g_xrinv);    SYMF(prB, g_rinvB);    SYMF(phr, g_hrinv);
    SYMF(pr2, g_rinv2);   SYMF(pcolsum, g_colsum);
    SYMF(pppre, g_ppre);  SYMF(ppsh, g_pshared); SYMF(ppb, g_pback);    SYMF(pops, g_outps);
    SYMF(phs, g_hshared); SYMF(ph2, g_hidden2);  SYMF(phip, g_hinfopre);
    SYMF(phi, g_hinfo);   SYMF(phb2, g_hback);   SYMF(pohs, g_ouths);
    SYMF(pind, g_indiv);  SYMF(poind, g_outindi);
    SYMI(pk1, g_keep1);   SYMI(pk2, g_keep2);
    SYMB(x_hi, g_x_hi);     SYMB(x_lo, g_x_lo);
    SYMB(xT_hi, g_xT_hi);   SYMB(xT_lo, g_xT_lo);
    SYMB(h1_hi, g_h1_hi);   SYMB(h1_lo, g_h1_lo);
    SYMB(hB_hi, g_hB_hi);   SYMB(hB_lo, g_hB_lo);
    SYMB(hBT_hi, g_hBT_hi); SYMB(hBT_lo, g_hBT_lo);
    SYMB(Lb_hi, g_Lb_hi);   SYMB(Lb_lo, g_Lb_lo);
    SYMB(hsh_hi, g_hsh_hi); SYMB(hsh_lo, g_hsh_lo);
    SYMB(h2_hi, g_h2_hi);   SYMB(h2_lo, g_h2_lo);
    SYMB(h2T_hi, g_h2T_hi); SYMB(h2T_lo, g_h2T_lo);
    SYMB(Sb_hi, g_Sb_hi);   SYMB(Sb_lo, g_Sb_lo);

    cudaFuncSetAttribute(bmma<0>, cudaFuncAttributeMaxDynamicSharedMemorySize, SM_BYTES);
    cudaFuncSetAttribute(bmma<1>, cudaFuncAttributeMaxDynamicSharedMemorySize, SM_BYTES);
    cudaFuncSetAttribute(bmma<2>, cudaFuncAttributeMaxDynamicSharedMemorySize, SM_BYTES);
    cudaFuncSetAttribute(bmma<3>, cudaFuncAttributeMaxDynamicSharedMemorySize, SM_BYTES);

    const size_t NH = (size_t)NST * HH;

    // zero accumulation targets
    kzero<<<8, 256>>>(pcsmv, CC);
    kzero<<<64, 256>>>(phB, (size_t)CC * HH);
    kzero<<<512, 256>>>(pppre, NH);
    kzero<<<512, 256>>>(ph2, NH);
    kzero<<<512, 256>>>(phip, NH);
    kzero<<<32, 256>>>(pcolsum, NST);

    // ---- stage 1: market-value concept aggregation --------------------------
    k_rowstats<<<NST, 128>>>(x, pxr, nullptr);
    k_split<<<512, 256>>>(x, x_hi, x_lo, NH);
    k_splitT<<<dim3(NST / 256, HH), 256>>>(x, xT_hi, xT_lo, NST, HH);
    k_csmv<<<dim3(CC / 128, 16), 128>>>(cm, mv);
    k_cagg<<<CC, 128>>>(cm, mv, x);
    k_rowstats<<<CC, 128>>>(ph1, nullptr, pk1);
    k_split<<<64, 256>>>(ph1, h1_hi, h1_lo, (size_t)CC * HH);

    // ---- stage 2: softmax-over-stocks re-aggregation (HMMA) ------------------
    bmma<0><<<dim3(NST / 128, CC / 128, 1), 256, SM_BYTES>>>(
        h1_hi, h1_lo, HH, x_hi, x_lo, HH, pL, NST, HH, nullptr, nullptr, nullptr);
    k_rowsoftmax_split<0><<<CC, 256, NST * 4>>>(pL, Lb_hi, Lb_lo, NST);
    bmma<2><<<dim3(1, CC / 128, 32), 256, SM_BYTES>>>(
        Lb_hi, Lb_lo, NST, xT_hi, xT_lo, NST, phB, HH, NST, nullptr, nullptr, nullptr);
    k_rowstats<<<CC, 128>>>(phB, prB, nullptr);
    k_split<<<64, 256>>>(phB, hB_hi, hB_lo, (size_t)CC * HH);
    k_splitT<<<dim3(CC / 256, HH), 256>>>(phB, hBT_hi, hBT_lo, CC, HH);

    // ---- stage 3: c2s attention -> p branch (HMMA) ---------------------------
    bmma<1><<<dim3(CC / 128, NST / 128, 1), 256, SM_BYTES>>>(
        x_hi, x_lo, HH, hB_hi, hB_lo, HH, pL, CC, HH, pxr, prB, pk1);
    k_rowsoftmax_split<1><<<NST, 256, CC * 4>>>(pL, Lb_hi, Lb_lo, CC);
    bmma<2><<<dim3(1, NST / 128, 4), 256, SM_BYTES>>>(
        Lb_hi, Lb_lo, CC, hBT_hi, hBT_lo, CC, pppre, HH, CC, nullptr, nullptr, nullptr);
    gemm128<2><<<dim3(1, NST / 128), 256>>>(pppre, W_ps, ppsh, NST, HH, HH, b_ps);
    gemm128<2><<<dim3(1, NST / 128), 256>>>(ppsh, W_psb, ppb, NST, HH, HH, b_psb);
    gemm128<3><<<dim3(1, NST / 128), 256>>>(ppsh, W_psf, pops, NST, HH, HH, b_psf);

    // ---- stage 4: hidden-similarity top-3 graph (HMMA, cos fused) ------------
    k_sub<<<512, 256>>>(x, ppb, phs, NH);
    k_rowstats<<<NST, 128>>>(phs, phr, nullptr);
    k_split<<<512, 256>>>(phs, hsh_hi, hsh_lo, NH);
    bmma<3><<<dim3(64, 64, 1), 256, SM_BYTES>>>(
        hsh_hi, hsh_lo, HH, hsh_hi, hsh_lo, HH, pS, NST, HH, phr, phr, nullptr);
    k_top3<<<NST, 256>>>();
    k_scatter<<<NST, 128>>>();
    k_diag<<<NST, 128>>>();

    // ---- stage 5: hc2s attention -> h branch (HMMA) ---------------------------
    k_split<<<512, 256>>>(ph2, h2_hi, h2_lo, NH);
    k_splitT<<<dim3(NST / 256, HH), 256>>>(ph2, h2T_hi, h2T_lo, NST, HH);
    bmma<1><<<dim3(64, 64, 1), 256, SM_BYTES>>>(
        hsh_hi, hsh_lo, HH, h2_hi, h2_lo, HH, pS, NST, HH, phr, pr2, pk2);
    k_rowsoftmax_split<1><<<NST, 256, NST * 4>>>(pS, Sb_hi, Sb_lo, NST);
    bmma<2><<<dim3(1, 64, 8), 256, SM_BYTES>>>(
        Sb_hi, Sb_lo, NST, h2T_hi, h2T_lo, NST, phip, HH, NST, nullptr, nullptr, nullptr);
    gemm128<2><<<dim3(1, NST / 128), 256>>>(phip, W_hs, phi, NST, HH, HH, b_hs);
    gemm128<2><<<dim3(1, NST / 128), 256>>>(phi, W_hsb, phb2, NST, HH, HH, b_hsb);
    gemm128<3><<<dim3(1, NST / 128), 256>>>(phi, W_hsf, pohs, NST, HH, HH, b_hsf);

    // ---- stage 6: individual branch + head -----------------------------------
    k_sub2<<<512, 256>>>(x, ppb, phb2, pind, NH);
    gemm128<3><<<dim3(1, NST / 128), 256>>>(pind, W_indi, poind, NST, HH, HH, b_indi);
    k_final<<<NST, 128>>>(W_out, b_out, out);
}